// round 9
// baseline (speedup 1.0000x reference)
#include <cuda_runtime.h>
#include <cuda_bf16.h>
#include <mma.h>
#include <cstdint>

using namespace nvcuda;

// ---------------------------------------------------------------------------
// Problem constants
// ---------------------------------------------------------------------------
#define BATCH 4
#define NSEQ  1024
#define DMODEL 1024
#define NHEAD 16
#define DK 64
#define MMEM 64
#define NKM (NSEQ + MMEM)   // 1088
#define EPS 1e-5f
#define NSLOTS 304          // ~2 CTAs/SM on 152 SMs

typedef __nv_bfloat16  bf16;
typedef __nv_bfloat162 bf162;

// ---------------------------------------------------------------------------
// Scratch + tile-ticket counters
// ---------------------------------------------------------------------------
__device__ bf16  g_xq[BATCH * NSEQ * DMODEL];
__device__ bf16  g_xk[BATCH * NSEQ * DMODEL];
__device__ bf16  g_xv[BATCH * NSEQ * DMODEL];
__device__ bf16  g_wq[DMODEL * DMODEL];
__device__ bf16  g_wk[DMODEL * DMODEL];
__device__ bf16  g_wv[DMODEL * DMODEL];
__device__ bf16  g_wo[DMODEL * DMODEL];
__device__ bf16  g_q   [BATCH * NSEQ * DMODEL];
__device__ bf16  g_k   [BATCH * NKM  * DMODEL];
__device__ bf16  g_v   [BATCH * NKM  * DMODEL];
__device__ bf16  g_attn[BATCH * NSEQ * DMODEL];
__device__ bf16  g_proj[BATCH * NSEQ * DMODEL];
__device__ int   c_qkv  = 0;   // reset by cvt_all (runs before QKV GEMM)
__device__ int   c_attn = 0;   // reset by fill_mem (runs before attention)
__device__ int   c_wo   = 0;   // reset by fill_mem (runs before Wo GEMM)

// ---------------------------------------------------------------------------
// helpers
// ---------------------------------------------------------------------------
__device__ __forceinline__ uint32_t smem_u32(const void* p) {
    return (uint32_t)__cvta_generic_to_shared(p);
}
__device__ __forceinline__ void cp16(uint32_t dst, const void* src) {
    asm volatile("cp.async.cg.shared.global [%0], [%1], 16;" :: "r"(dst), "l"(src));
}
__device__ __forceinline__ void cp_commit() {
    asm volatile("cp.async.commit_group;");
}
template<int N> __device__ __forceinline__ void cp_wait() {
    asm volatile("cp.async.wait_group %0;" :: "n"(N));
}
__device__ __forceinline__ uint32_t lds_u32(uint32_t a) {
    uint32_t v;
    asm volatile("ld.shared.b32 %0, [%1];" : "=r"(v) : "r"(a));
    return v;
}
__device__ __forceinline__ void ldsm_x4(uint32_t& d0, uint32_t& d1,
                                        uint32_t& d2, uint32_t& d3, uint32_t a) {
    asm volatile("ldmatrix.sync.aligned.m8n8.x4.shared.b16 {%0,%1,%2,%3}, [%4];"
                 : "=r"(d0), "=r"(d1), "=r"(d2), "=r"(d3) : "r"(a));
}
__device__ __forceinline__ void ldsm_x4_trans(uint32_t& d0, uint32_t& d1,
                                              uint32_t& d2, uint32_t& d3, uint32_t a) {
    asm volatile("ldmatrix.sync.aligned.m8n8.x4.trans.shared.b16 {%0,%1,%2,%3}, [%4];"
                 : "=r"(d0), "=r"(d1), "=r"(d2), "=r"(d3) : "r"(a));
}
__device__ __forceinline__ void mma16816(float& c0, float& c1, float& c2, float& c3,
                                         uint32_t a0, uint32_t a1, uint32_t a2, uint32_t a3,
                                         uint32_t b0, uint32_t b1) {
    asm volatile("mma.sync.aligned.m16n8k16.row.col.f32.bf16.bf16.f32 "
                 "{%0,%1,%2,%3}, {%4,%5,%6,%7}, {%8,%9}, {%0,%1,%2,%3};"
                 : "+f"(c0), "+f"(c1), "+f"(c2), "+f"(c3)
                 : "r"(a0), "r"(a1), "r"(a2), "r"(a3), "r"(b0), "r"(b1));
}
__device__ __forceinline__ uint32_t pack_bf16x2(float lo, float hi) {
    bf162 t = __floats2bfloat162_rn(lo, hi);
    return *(uint32_t*)&t;
}

// ---------------------------------------------------------------------------
// fp32 -> bf16 conversion, 7 tensors in one launch (grid.y = job).
// Also resets the QKV GEMM ticket counter.
// ---------------------------------------------------------------------------
struct CvtJob { const float* in; bf16* out; int n; };

__global__ __launch_bounds__(256) void cvt_all(
    CvtJob j0, CvtJob j1, CvtJob j2, CvtJob j3, CvtJob j4, CvtJob j5, CvtJob j6)
{
    if (blockIdx.x == 0 && blockIdx.y == 0 && threadIdx.x == 0) c_qkv = 0;
    CvtJob j;
    switch (blockIdx.y) {
        case 0: j = j0; break; case 1: j = j1; break; case 2: j = j2; break;
        case 3: j = j3; break; case 4: j = j4; break; case 5: j = j5; break;
        default: j = j6; break;
    }
    int i = (blockIdx.x * 256 + threadIdx.x) * 8;
    if (i >= j.n) return;
    float4 v0 = *(const float4*)(j.in + i);
    float4 v1 = *(const float4*)(j.in + i + 4);
    uint4 o;
    o.x = pack_bf16x2(v0.x, v0.y); o.y = pack_bf16x2(v0.z, v0.w);
    o.z = pack_bf16x2(v1.x, v1.y); o.w = pack_bf16x2(v1.z, v1.w);
    *(uint4*)(j.out + i) = o;
}

// ---------------------------------------------------------------------------
// BF16 GEMM, C = A @ W^T + bias (bf16 out). 128x128 tile, BK=64, 3-stage
// cp.async, 8 warps, 2 CTAs/SM. PERSISTENT: CTAs pull tiles from a ticket.
// Tile decode: z = t/256 (job), rem = t%256, by = rem/8, bx = rem%8.
// ---------------------------------------------------------------------------
#define BM 128
#define BN 128
#define BKD 64
#define PKH 72
#define STAGEH (BM * PKH)                        // 9216 halves
#define GEMM_SMEM_BYTES (6 * STAGEH * 2)         // 110592 B
#define EPI_LD 132

struct GemmJob {
    const bf16* A; const bf16* W; const float* bias; bf16* C; int rows_out;
};

__global__ __launch_bounds__(256, 2) void gemm_bf16(
    GemmJob j0, GemmJob j1, GemmJob j2, int* ctr, int ntiles)
{
    extern __shared__ bf16 smh[];
    __shared__ int s_tile;
    bf16* Abuf[3] = { smh, smh + 2 * STAGEH, smh + 4 * STAGEH };
    bf16* Bbuf[3] = { smh + STAGEH, smh + 3 * STAGEH, smh + 5 * STAGEH };

    const int tid  = threadIdx.x;
    const int warp = tid >> 5;
    const int wr   = warp & 3;
    const int wc   = warp >> 2;
    const int K = DMODEL;
    const int NIT = K / BKD;   // 16
    const int lr = tid >> 3, lc = tid & 7;

    for (;;) {
        if (tid == 0) s_tile = atomicAdd(ctr, 1);
        __syncthreads();                  // ticket visible + prev tile's smem free
        const int t = s_tile;
        if (t >= ntiles) return;

        const GemmJob j = (t < 256) ? j0 : (t < 512 ? j1 : j2);
        const int rem  = t & 255;
        const int row0 = (rem >> 3) * BM;
        const int col0 = (rem & 7) * BN;

        wmma::fragment<wmma::accumulator, 16, 16, 16, float> acc[2][4];
#pragma unroll
        for (int i = 0; i < 2; i++)
#pragma unroll
            for (int c = 0; c < 4; c++) wmma::fill_fragment(acc[i][c], 0.0f);

        // prologue: stages 0,1
#pragma unroll
        for (int s = 0; s < 2; s++) {
            int kb = s * BKD;
#pragma unroll
            for (int tt = 0; tt < 4; tt++) {
                int r = lr + tt * 32;
                cp16(smem_u32(&Abuf[s][r * PKH + lc * 8]), &j.A[(size_t)(row0 + r) * K + kb + lc * 8]);
                cp16(smem_u32(&Bbuf[s][r * PKH + lc * 8]), &j.W[(size_t)(col0 + r) * K + kb + lc * 8]);
            }
            cp_commit();
        }

        for (int it = 0; it < NIT; ++it) {
            if (it + 1 < NIT) cp_wait<1>(); else cp_wait<0>();
            __syncthreads();

            if (it + 2 < NIT) {
                int kb = (it + 2) * BKD;
                int st = (it + 2) % 3;
#pragma unroll
                for (int tt = 0; tt < 4; tt++) {
                    int r = lr + tt * 32;
                    cp16(smem_u32(&Abuf[st][r * PKH + lc * 8]), &j.A[(size_t)(row0 + r) * K + kb + lc * 8]);
                    cp16(smem_u32(&Bbuf[st][r * PKH + lc * 8]), &j.W[(size_t)(col0 + r) * K + kb + lc * 8]);
                }
                cp_commit();
            }

            const bf16* Ap = Abuf[it % 3];
            const bf16* Bp = Bbuf[it % 3];
#pragma unroll
            for (int ks = 0; ks < BKD / 16; ks++) {
                wmma::fragment<wmma::matrix_a, 16, 16, 16, bf16, wmma::row_major> a0, a1;
                wmma::fragment<wmma::matrix_b, 16, 16, 16, bf16, wmma::col_major> b[4];
                wmma::load_matrix_sync(a0, &Ap[(wr * 32     ) * PKH + ks * 16], PKH);
                wmma::load_matrix_sync(a1, &Ap[(wr * 32 + 16) * PKH + ks * 16], PKH);
#pragma unroll
                for (int c = 0; c < 4; c++)
                    wmma::load_matrix_sync(b[c], &Bp[(wc * 64 + c * 16) * PKH + ks * 16], PKH);
#pragma unroll
                for (int c = 0; c < 4; c++) {
                    wmma::mma_sync(acc[0][c], a0, b[c], acc[0][c]);
                    wmma::mma_sync(acc[1][c], a1, b[c], acc[1][c]);
                }
            }
        }
        __syncthreads();   // before epilogue smem alias

        float (*Cs)[EPI_LD] = (float (*)[EPI_LD])smh;
#pragma unroll
        for (int i = 0; i < 2; i++)
#pragma unroll
            for (int c = 0; c < 4; c++)
                wmma::store_matrix_sync(&Cs[wr * 32 + i * 16][wc * 64 + c * 16],
                                        acc[i][c], EPI_LD, wmma::mem_row_major);
        __syncthreads();

        const int bidx  = row0 >> 10;
        const int obase = bidx * j.rows_out + (row0 & 1023);
#pragma unroll
        for (int tt = 0; tt < 8; tt++) {
            int ch = tid + tt * 256;
            int r = ch >> 4, c8 = ch & 15;
            const float* src = &Cs[r][c8 * 8];
            const float* bp  = &j.bias[col0 + c8 * 8];
            uint4 o;
            o.x = pack_bf16x2(src[0] + bp[0], src[1] + bp[1]);
            o.y = pack_bf16x2(src[2] + bp[2], src[3] + bp[3]);
            o.z = pack_bf16x2(src[4] + bp[4], src[5] + bp[5]);
            o.w = pack_bf16x2(src[6] + bp[6], src[7] + bp[7]);
            *(uint4*)&j.C[(size_t)(obase + r) * DMODEL + col0 + c8 * 8] = o;
        }
        // next iteration's ticket __syncthreads guards smem reuse
    }
}

// ---------------------------------------------------------------------------
// Memory-token rows of K/V (both scales = 8.0), bf16.
// Also resets the attention and Wo ticket counters.
// ---------------------------------------------------------------------------
__global__ void fill_mem(const float* __restrict__ m_k, const float* __restrict__ m_v)
{
    int idx = blockIdx.x * blockDim.x + threadIdx.x;
    if (idx == 0) { c_attn = 0; c_wo = 0; }
    if (idx >= BATCH * MMEM * DMODEL) return;
    int d = idx & (DMODEL - 1);
    int m = (idx >> 10) & (MMEM - 1);
    int b = idx >> 16;
    size_t off = ((size_t)(b * NKM + NSEQ + m)) * DMODEL + d;
    g_k[off] = __float2bfloat16(m_k[m * DMODEL + d] * 8.0f);
    g_v[off] = __float2bfloat16(m_v[m * DMODEL + d] * 8.0f);
}

// ---------------------------------------------------------------------------
// Attention via raw mma.sync (FA2-style register pipeline). PERSISTENT:
// CTAs pull (qt,h,b) tiles from a ticket. Tile decode: qt = t&7 (fastest,
// so consecutive tickets share K/V in L2), h = (t>>3)&15, b = t>>7.
// No-rescale softmax (scores O(1): implicit max = 0; memory block unmasked).
// ---------------------------------------------------------------------------
#define LDQ 72
#define LDKV 72
#define ATTN_SMEM_BYTES ((128 * LDQ + 4 * 64 * LDKV) * 2 + NSEQ * 4)  // 59392
#define ATTN_TILES (8 * NHEAD * BATCH)   // 512

__global__ __launch_bounds__(256, 2) void attn_kernel(const int* __restrict__ amask)
{
    extern __shared__ char smraw[];
    __shared__ int s_tile;
    bf16* Qs  = (bf16*)smraw;
    bf16* Kb0 = Qs + 128 * LDQ;
    bf16* Kb1 = Kb0 + 64 * LDKV;
    bf16* Vb0 = Kb1 + 64 * LDKV;
    bf16* Vb1 = Vb0 + 64 * LDKV;
    int*  msk = (int*)(Vb1 + 64 * LDKV);

    const int tid  = threadIdx.x;
    const int warp = tid >> 5;
    const int lane = tid & 31;
    const int r = lane >> 2;
    const int c = lane & 3;
    const int lr = tid >> 3, lc8 = tid & 7;
    const int lrow8 = lane & 7;
    const int ksel  = (lane >> 3) & 1;
    const int nsel  = (lane >> 4) & 1;
    const int g  = lane >> 3;
    const int rw = lane & 7;

    for (;;) {
        if (tid == 0) s_tile = atomicAdd(&c_attn, 1);
        __syncthreads();               // ticket visible + prev tile's smem free
        const int t = s_tile;
        if (t >= ATTN_TILES) return;
        const int qt = t & 7;
        const int h  = (t >> 3) & 15;
        const int b  = t >> 7;

        const bf16* qbase = g_q + ((size_t)(b * NSEQ + qt * 128)) * DMODEL + h * DK;
        const bf16* kroot = g_k + ((size_t)(b * NKM)) * DMODEL + h * DK;
        const bf16* vroot = g_v + ((size_t)(b * NKM)) * DMODEL + h * DK;

        // group 0: Q + mask
#pragma unroll
        for (int tt = 0; tt < 4; tt++) {
            int row = lr + tt * 32;
            cp16(smem_u32(&Qs[row * LDQ + lc8 * 8]), &qbase[(size_t)row * DMODEL + lc8 * 8]);
        }
        cp16(smem_u32(&msk[tid * 4]), &amask[b * NSEQ + tid * 4]);
        cp_commit();

        // group 1: K/V block 0
#pragma unroll
        for (int tt = 0; tt < 2; tt++) {
            int row = lr + tt * 32;
            cp16(smem_u32(&Kb0[row * LDKV + lc8 * 8]), &kroot[(size_t)row * DMODEL + lc8 * 8]);
            cp16(smem_u32(&Vb0[row * LDKV + lc8 * 8]), &vroot[(size_t)row * DMODEL + lc8 * 8]);
        }
        cp_commit();

        cp_wait<1>();          // Q + mask complete
        __syncthreads();

        // Q fragments (A-layout, m16n8k16)
        uint32_t qf[4][4];
        {
            uint32_t q0 = smem_u32(&Qs[(warp * 16 + r) * LDQ]) + 4 * c;
            uint32_t q8 = q0 + 8 * LDQ * 2;
#pragma unroll
            for (int kc = 0; kc < 4; kc++) {
                qf[kc][0] = lds_u32(q0 + kc * 32);
                qf[kc][1] = lds_u32(q8 + kc * 32);
                qf[kc][2] = lds_u32(q0 + kc * 32 + 16);
                qf[kc][3] = lds_u32(q8 + kc * 32 + 16);
            }
        }

        float oacc[8][4];
#pragma unroll
        for (int ot = 0; ot < 8; ot++)
#pragma unroll
            for (int i = 0; i < 4; i++) oacc[ot][i] = 0.0f;
        float sum0 = 0.0f, sum1 = 0.0f;

        for (int kb = 0; kb < 17; kb++) {
            const bf16* Kp = (kb & 1) ? Kb1 : Kb0;
            const bf16* Vp = (kb & 1) ? Vb1 : Vb0;

            cp_wait<0>();      // K/V block kb resident
            __syncthreads();   // all warps done with the buffer we prefetch into

            if (kb + 1 < 17) {
                bf16* Kn = (kb & 1) ? Kb0 : Kb1;
                bf16* Vn = (kb & 1) ? Vb0 : Vb1;
                const bf16* kp = kroot + (size_t)(kb + 1) * 64 * DMODEL;
                const bf16* vp = vroot + (size_t)(kb + 1) * 64 * DMODEL;
#pragma unroll
                for (int tt = 0; tt < 2; tt++) {
                    int row = lr + tt * 32;
                    cp16(smem_u32(&Kn[row * LDKV + lc8 * 8]), &kp[(size_t)row * DMODEL + lc8 * 8]);
                    cp16(smem_u32(&Vn[row * LDKV + lc8 * 8]), &vp[(size_t)row * DMODEL + lc8 * 8]);
                }
                cp_commit();
            }

            // ---- S = Q @ K^T : K fragments via ldmatrix.x4 ----
            float sc[8][4];
#pragma unroll
            for (int nt = 0; nt < 8; nt++)
#pragma unroll
                for (int i = 0; i < 4; i++) sc[nt][i] = 0.0f;

            const uint32_t kfb = smem_u32(Kp) + ((nsel * 8 + lrow8) * LDKV + ksel * 8) * 2;
#pragma unroll
            for (int kc = 0; kc < 4; kc++) {
#pragma unroll
                for (int ng = 0; ng < 4; ng++) {
                    uint32_t b0, b1, b2, b3;
                    ldsm_x4(b0, b1, b2, b3, kfb + (ng * 16 * LDKV + kc * 16) * 2);
                    mma16816(sc[2 * ng][0], sc[2 * ng][1], sc[2 * ng][2], sc[2 * ng][3],
                             qf[kc][0], qf[kc][1], qf[kc][2], qf[kc][3], b0, b1);
                    mma16816(sc[2 * ng + 1][0], sc[2 * ng + 1][1], sc[2 * ng + 1][2], sc[2 * ng + 1][3],
                             qf[kc][0], qf[kc][1], qf[kc][2], qf[kc][3], b2, b3);
                }
            }

            // ---- mask + exp in registers; pack P into A-fragment halves ----
            uint32_t pf[8][2];
            const bool mb = (kb < 16);
            const int colbase = kb * 64 + 2 * c;
#pragma unroll
            for (int nt = 0; nt < 8; nt++) {
                int col = colbase + nt * 8;
                bool m0 = mb && (msk[col] != 0);
                bool m1 = mb && (msk[col + 1] != 0);
                float p00 = m0 ? 0.0f : __expf(sc[nt][0] * 0.125f);
                float p01 = m1 ? 0.0f : __expf(sc[nt][1] * 0.125f);
                float p10 = m0 ? 0.0f : __expf(sc[nt][2] * 0.125f);
                float p11 = m1 ? 0.0f : __expf(sc[nt][3] * 0.125f);
                sum0 += p00 + p01;
                sum1 += p10 + p11;
                pf[nt][0] = pack_bf16x2(p00, p01);
                pf[nt][1] = pack_bf16x2(p10, p11);
            }

            // ---- O += P @ V (B fragments via ldmatrix.trans from V tile) ----
            const uint32_t vbase = smem_u32(Vp);
#pragma unroll
            for (int kc = 0; kc < 4; kc++) {
                uint32_t a0 = pf[2 * kc][0], a1 = pf[2 * kc][1];
                uint32_t a2 = pf[2 * kc + 1][0], a3 = pf[2 * kc + 1][1];
#pragma unroll
                for (int op = 0; op < 4; op++) {
                    uint32_t addr = vbase +
                        ((16 * kc + (g & 1) * 8 + rw) * LDKV + (op * 2 + (g >> 1)) * 8) * 2;
                    uint32_t b0, b1, b2, b3;
                    ldsm_x4_trans(b0, b1, b2, b3, addr);
                    mma16816(oacc[op * 2][0], oacc[op * 2][1], oacc[op * 2][2], oacc[op * 2][3],
                             a0, a1, a2, a3, b0, b1);
                    mma16816(oacc[op * 2 + 1][0], oacc[op * 2 + 1][1],
                             oacc[op * 2 + 1][2], oacc[op * 2 + 1][3],
                             a0, a1, a2, a3, b2, b3);
                }
            }
        }

        sum0 += __shfl_xor_sync(0xffffffffu, sum0, 1);
        sum0 += __shfl_xor_sync(0xffffffffu, sum0, 2);
        sum1 += __shfl_xor_sync(0xffffffffu, sum1, 1);
        sum1 += __shfl_xor_sync(0xffffffffu, sum1, 2);
        const float inv0 = 1.0f / sum0;
        const float inv1 = 1.0f / sum1;

        bf16* ob = g_attn + ((size_t)(b * NSEQ + qt * 128 + warp * 16 + r)) * DMODEL + h * DK + 2 * c;
#pragma unroll
        for (int ot = 0; ot < 8; ot++) {
            *(uint32_t*)&ob[ot * 8] =
                pack_bf16x2(oacc[ot][0] * inv0, oacc[ot][1] * inv0);
            *(uint32_t*)&ob[8 * DMODEL + ot * 8] =
                pack_bf16x2(oacc[ot][2] * inv1, oacc[ot][3] * inv1);
        }
        // next iteration's ticket __syncthreads guards smem reuse
    }
}

// ---------------------------------------------------------------------------
// Residual + LayerNorm. One warp per row. proj is bf16.
// ---------------------------------------------------------------------------
__global__ __launch_bounds__(256) void ln_kernel(
    const float* __restrict__ queries, const float* __restrict__ gamma,
    const float* __restrict__ beta, float* __restrict__ out)
{
    const int row  = blockIdx.x * 8 + (threadIdx.x >> 5);
    const int lane = threadIdx.x & 31;
    const float4* xin = (const float4*)(queries + (size_t)row * DMODEL);
    const uint4*  pin = (const uint4*)(g_proj + (size_t)row * DMODEL);

    float x[32];
    float s = 0.0f;
#pragma unroll
    for (int i = 0; i < 4; i++) {
        int ch = lane + i * 32;               // 8 floats per chunk
        float4 a0 = xin[ch * 2];
        float4 a1 = xin[ch * 2 + 1];
        uint4 p = pin[ch];
        const bf162* ph = (const bf162*)&p;
        float2 p0 = __bfloat1622float2(ph[0]);
        float2 p1 = __bfloat1622float2(ph[1]);
        float2 p2 = __bfloat1622float2(ph[2]);
        float2 p3 = __bfloat1622float2(ph[3]);
        x[i * 8 + 0] = a0.x + p0.x; x[i * 8 + 1] = a0.y + p0.y;
        x[i * 8 + 2] = a0.z + p1.x; x[i * 8 + 3] = a0.w + p1.y;
        x[i * 8 + 4] = a1.x + p2.x; x[i * 8 + 5] = a1.y + p2.y;
        x[i * 8 + 6] = a1.z + p3.x; x[i * 8 + 7] = a1.w + p3.y;
#pragma unroll
        for (int k = 0; k < 8; k++) s += x[i * 8 + k];
    }
#pragma unroll
    for (int o = 16; o; o >>= 1) s += __shfl_xor_sync(0xffffffffu, s, o);
    const float mu = s * (1.0f / DMODEL);

    float v = 0.0f;
#pragma unroll
    for (int i = 0; i < 32; i++) { float d = x[i] - mu; v += d * d; }
#pragma unroll
    for (int o = 16; o; o >>= 1) v += __shfl_xor_sync(0xffffffffu, v, o);
    const float rs = rsqrtf(v * (1.0f / DMODEL) + EPS);

    float4* op = (float4*)(out + (size_t)row * DMODEL);
    const float4* gp = (const float4*)gamma;
    const float4* bp = (const float4*)beta;
#pragma unroll
    for (int i = 0; i < 4; i++) {
        int ch = lane + i * 32;               // same chunk layout as fill loop
#pragma unroll
        for (int half = 0; half < 2; half++) {
            float4 g  = gp[ch * 2 + half];
            float4 be = bp[ch * 2 + half];
            float4 o4;
            o4.x = (x[i * 8 + half * 4 + 0] - mu) * rs * g.x + be.x;
            o4.y = (x[i * 8 + half * 4 + 1] - mu) * rs * g.y + be.y;
            o4.z = (x[i * 8 + half * 4 + 2] - mu) * rs * g.z + be.z;
            o4.w = (x[i * 8 + half * 4 + 3] - mu) * rs * g.w + be.w;
            op[ch * 2 + half] = o4;
        }
    }
}

// ---------------------------------------------------------------------------
// Launch
// ---------------------------------------------------------------------------
extern "C" void kernel_launch(void* const* d_in, const int* in_sizes, int n_in,
                              void* d_out, int out_size)
{
    const float* queries = (const float*)d_in[0];
    const float* keys    = (const float*)d_in[1];
    const float* values  = (const float*)d_in[2];
    const int*   amask   = (const int*)  d_in[3];
    const float* Wq = (const float*)d_in[4],  *bq = (const float*)d_in[5];
    const float* Wk = (const float*)d_in[6],  *bk = (const float*)d_in[7];
    const float* Wv = (const float*)d_in[8],  *bv = (const float*)d_in[9];
    const float* Wo = (const float*)d_in[10], *bo = (const float*)d_in[11];
    const float* m_k = (const float*)d_in[12], *m_v = (const float*)d_in[13];
    const float* gamma = (const float*)d_in[14], *beta = (const float*)d_in[15];
    float* out = (float*)d_out;

    bf16 *xq, *xk, *xv, *wq, *wk, *wv, *wo, *pq, *pk, *pv, *pa, *pp;
    cudaGetSymbolAddress((void**)&xq, g_xq);
    cudaGetSymbolAddress((void**)&xk, g_xk);
    cudaGetSymbolAddress((void**)&xv, g_xv);
    cudaGetSymbolAddress((void**)&wq, g_wq);
    cudaGetSymbolAddress((void**)&wk, g_wk);
    cudaGetSymbolAddress((void**)&wv, g_wv);
    cudaGetSymbolAddress((void**)&wo, g_wo);
    cudaGetSymbolAddress((void**)&pq, g_q);
    cudaGetSymbolAddress((void**)&pk, g_k);
    cudaGetSymbolAddress((void**)&pv, g_v);
    cudaGetSymbolAddress((void**)&pa, g_attn);
    cudaGetSymbolAddress((void**)&pp, g_proj);
    int *ctr_qkv, *ctr_wo;
    cudaGetSymbolAddress((void**)&ctr_qkv, c_qkv);
    cudaGetSymbolAddress((void**)&ctr_wo,  c_wo);

    cudaFuncSetAttribute(gemm_bf16,
                         cudaFuncAttributeMaxDynamicSharedMemorySize, GEMM_SMEM_BYTES);
    cudaFuncSetAttribute(attn_kernel,
                         cudaFuncAttributeMaxDynamicSharedMemorySize, ATTN_SMEM_BYTES);

    const int Mrows = BATCH * NSEQ;        // 4096
    const int NACT  = Mrows * DMODEL;      // 4M
    const int NWEI  = DMODEL * DMODEL;     // 1M

    CvtJob cj0 = { queries, xq, NACT };
    CvtJob cj1 = { keys,    xk, NACT };
    CvtJob cj2 = { values,  xv, NACT };
    CvtJob cj3 = { Wq, wq, NWEI };
    CvtJob cj4 = { Wk, wk, NWEI };
    CvtJob cj5 = { Wv, wv, NWEI };
    CvtJob cj6 = { Wo, wo, NWEI };
    cvt_all<<<dim3(NACT / 2048, 7), 256>>>(cj0, cj1, cj2, cj3, cj4, cj5, cj6);

    GemmJob jq = { xq, wq, bq, pq, NSEQ };
    GemmJob jk = { xk, wk, bk, pk, NKM  };
    GemmJob jv = { xv, wv, bv, pv, NKM  };
    GemmJob jo = { pa, wo, bo, pp, NSEQ };

    // fused Q/K/V projections: 768 tiles, persistent CTAs
    gemm_bf16<<<NSLOTS, 256, GEMM_SMEM_BYTES>>>(jq, jk, jv, ctr_qkv, 768);

    fill_mem<<<(BATCH * MMEM * DMODEL + 255) / 256, 256>>>(m_k, m_v);

    // attention: 512 tiles, persistent CTAs
    attn_kernel<<<NSLOTS, 256, ATTN_SMEM_BYTES>>>(amask);

    // output projection: 256 tiles
    gemm_bf16<<<256, 256, GEMM_SMEM_BYTES>>>(jo, jo, jo, ctr_wo, 256);

    ln_kernel<<<Mrows / 8, 256>>>(queries, gamma, beta, out);
}

// round 10
// speedup vs baseline: 1.2722x; 1.2722x over previous
#include <cuda_runtime.h>
#include <cuda_bf16.h>
#include <mma.h>
#include <cstdint>

using namespace nvcuda;

// ---------------------------------------------------------------------------
// Problem constants
// ---------------------------------------------------------------------------
#define BATCH 4
#define NSEQ  1024
#define DMODEL 1024
#define NHEAD 16
#define DK 64
#define MMEM 64
#define NKM (NSEQ + MMEM)   // 1088
#define EPS 1e-5f

typedef __nv_bfloat16  bf16;
typedef __nv_bfloat162 bf162;

// ---------------------------------------------------------------------------
// Scratch
// ---------------------------------------------------------------------------
__device__ bf16  g_xq[BATCH * NSEQ * DMODEL];
__device__ bf16  g_xk[BATCH * NSEQ * DMODEL];
__device__ bf16  g_xv[BATCH * NSEQ * DMODEL];
__device__ bf16  g_wq[DMODEL * DMODEL];
__device__ bf16  g_wk[DMODEL * DMODEL];
__device__ bf16  g_wv[DMODEL * DMODEL];
__device__ bf16  g_wo[DMODEL * DMODEL];
__device__ bf16  g_q   [BATCH * NSEQ * DMODEL];
__device__ bf16  g_k   [BATCH * NSEQ * DMODEL];   // projected K (seq rows only)
__device__ bf16  g_v   [BATCH * NSEQ * DMODEL];
__device__ bf16  g_kc  [BATCH * NKM  * DMODEL];   // compacted K (+mem, +pad)
__device__ bf16  g_vc  [BATCH * NKM  * DMODEL];
__device__ bf16  g_attn[BATCH * NSEQ * DMODEL];
__device__ bf16  g_proj[BATCH * NSEQ * DMODEL];
__device__ int   g_pos [BATCH * NSEQ];            // compaction target (-1 = masked)
__device__ int   g_nk  [BATCH];                   // survivors per batch

// ---------------------------------------------------------------------------
// helpers
// ---------------------------------------------------------------------------
__device__ __forceinline__ uint32_t smem_u32(const void* p) {
    return (uint32_t)__cvta_generic_to_shared(p);
}
__device__ __forceinline__ void cp16(uint32_t dst, const void* src) {
    asm volatile("cp.async.cg.shared.global [%0], [%1], 16;" :: "r"(dst), "l"(src));
}
__device__ __forceinline__ void cp_commit() {
    asm volatile("cp.async.commit_group;");
}
template<int N> __device__ __forceinline__ void cp_wait() {
    asm volatile("cp.async.wait_group %0;" :: "n"(N));
}
__device__ __forceinline__ uint32_t lds_u32(uint32_t a) {
    uint32_t v;
    asm volatile("ld.shared.b32 %0, [%1];" : "=r"(v) : "r"(a));
    return v;
}
__device__ __forceinline__ void ldsm_x4(uint32_t& d0, uint32_t& d1,
                                        uint32_t& d2, uint32_t& d3, uint32_t a) {
    asm volatile("ldmatrix.sync.aligned.m8n8.x4.shared.b16 {%0,%1,%2,%3}, [%4];"
                 : "=r"(d0), "=r"(d1), "=r"(d2), "=r"(d3) : "r"(a));
}
__device__ __forceinline__ void ldsm_x4_trans(uint32_t& d0, uint32_t& d1,
                                              uint32_t& d2, uint32_t& d3, uint32_t a) {
    asm volatile("ldmatrix.sync.aligned.m8n8.x4.trans.shared.b16 {%0,%1,%2,%3}, [%4];"
                 : "=r"(d0), "=r"(d1), "=r"(d2), "=r"(d3) : "r"(a));
}
__device__ __forceinline__ void mma16816(float& c0, float& c1, float& c2, float& c3,
                                         uint32_t a0, uint32_t a1, uint32_t a2, uint32_t a3,
                                         uint32_t b0, uint32_t b1) {
    asm volatile("mma.sync.aligned.m16n8k16.row.col.f32.bf16.bf16.f32 "
                 "{%0,%1,%2,%3}, {%4,%5,%6,%7}, {%8,%9}, {%0,%1,%2,%3};"
                 : "+f"(c0), "+f"(c1), "+f"(c2), "+f"(c3)
                 : "r"(a0), "r"(a1), "r"(a2), "r"(a3), "r"(b0), "r"(b1));
}
__device__ __forceinline__ uint32_t pack_bf16x2(float lo, float hi) {
    bf162 t = __floats2bfloat162_rn(lo, hi);
    return *(uint32_t*)&t;
}

// ---------------------------------------------------------------------------
// fp32 -> bf16 conversion, 7 tensors in one launch (grid.y = job).
// ---------------------------------------------------------------------------
struct CvtJob { const float* in; bf16* out; int n; };

__global__ __launch_bounds__(256) void cvt_all(
    CvtJob j0, CvtJob j1, CvtJob j2, CvtJob j3, CvtJob j4, CvtJob j5, CvtJob j6)
{
    CvtJob j;
    switch (blockIdx.y) {
        case 0: j = j0; break; case 1: j = j1; break; case 2: j = j2; break;
        case 3: j = j3; break; case 4: j = j4; break; case 5: j = j5; break;
        default: j = j6; break;
    }
    int i = (blockIdx.x * 256 + threadIdx.x) * 8;
    if (i >= j.n) return;
    float4 v0 = *(const float4*)(j.in + i);
    float4 v1 = *(const float4*)(j.in + i + 4);
    uint4 o;
    o.x = pack_bf16x2(v0.x, v0.y); o.y = pack_bf16x2(v0.z, v0.w);
    o.z = pack_bf16x2(v1.x, v1.y); o.w = pack_bf16x2(v1.z, v1.w);
    *(uint4*)(j.out + i) = o;
}

// ---------------------------------------------------------------------------
// Mask scan: per batch, exclusive prefix positions of unmasked columns.
// ---------------------------------------------------------------------------
__global__ __launch_bounds__(1024) void mask_scan(const int* __restrict__ amask)
{
    const int b = blockIdx.x;
    const int i = threadIdx.x;
    const int lane = i & 31, w = i >> 5;
    int keep = (amask[b * NSEQ + i] == 0) ? 1 : 0;
    unsigned bal = __ballot_sync(0xffffffffu, keep);
    int before = __popc(bal & ((1u << lane) - 1));
    __shared__ int wsum[32];
    if (lane == 0) wsum[w] = __popc(bal);
    __syncthreads();
    if (w == 0) {
        int v = wsum[lane];
#pragma unroll
        for (int o = 1; o < 32; o <<= 1) {
            int t = __shfl_up_sync(0xffffffffu, v, o);
            if (lane >= o) v += t;
        }
        wsum[lane] = v;   // inclusive scan of warp counts
    }
    __syncthreads();
    int base = (w == 0) ? 0 : wsum[w - 1];
    g_pos[b * NSEQ + i] = keep ? (base + before) : -1;
    if (i == 1023) g_nk[b] = wsum[31];
}

// ---------------------------------------------------------------------------
// Compact K/V rows: survivors first, 64 memory rows (x8) appended, zero pad
// to the next multiple of 64. 128 threads copy one 1024-bf16 row (K and V).
// ---------------------------------------------------------------------------
__global__ __launch_bounds__(128) void compact_kv(
    const float* __restrict__ m_k, const float* __restrict__ m_v)
{
    const int b = blockIdx.y;
    const int x = blockIdx.x;      // 0..1151
    const int t = threadIdx.x;     // 128
    const int nk = g_nk[b];

    if (x < NSEQ) {
        int pos = g_pos[b * NSEQ + x];
        if (pos < 0) return;
        const uint4* ks = (const uint4*)(g_k + ((size_t)(b * NSEQ + x)) * DMODEL);
        const uint4* vs = (const uint4*)(g_v + ((size_t)(b * NSEQ + x)) * DMODEL);
        uint4* kd = (uint4*)(g_kc + ((size_t)(b * NKM + pos)) * DMODEL);
        uint4* vd = (uint4*)(g_vc + ((size_t)(b * NKM + pos)) * DMODEL);
        kd[t] = ks[t];
        vd[t] = vs[t];
    } else if (x < NSEQ + MMEM) {
        int m = x - NSEQ;
        int dst = nk + m;
        const float4* mk = (const float4*)(m_k + (size_t)m * DMODEL);
        const float4* mv = (const float4*)(m_v + (size_t)m * DMODEL);
        float4 a0 = mk[t * 2], a1 = mk[t * 2 + 1];
        float4 b0 = mv[t * 2], b1 = mv[t * 2 + 1];
        uint4 ko, vo;
        ko.x = pack_bf16x2(a0.x * 8.f, a0.y * 8.f); ko.y = pack_bf16x2(a0.z * 8.f, a0.w * 8.f);
        ko.z = pack_bf16x2(a1.x * 8.f, a1.y * 8.f); ko.w = pack_bf16x2(a1.z * 8.f, a1.w * 8.f);
        vo.x = pack_bf16x2(b0.x * 8.f, b0.y * 8.f); vo.y = pack_bf16x2(b0.z * 8.f, b0.w * 8.f);
        vo.z = pack_bf16x2(b1.x * 8.f, b1.y * 8.f); vo.w = pack_bf16x2(b1.z * 8.f, b1.w * 8.f);
        ((uint4*)(g_kc + ((size_t)(b * NKM + dst)) * DMODEL))[t] = ko;
        ((uint4*)(g_vc + ((size_t)(b * NKM + dst)) * DMODEL))[t] = vo;
    } else {
        int p = x - NSEQ - MMEM;
        int dst = nk + MMEM + p;
        int KB = (nk + 127) >> 6;
        if (dst >= (KB << 6)) return;
        uint4 z = {0, 0, 0, 0};
        ((uint4*)(g_kc + ((size_t)(b * NKM + dst)) * DMODEL))[t] = z;
        ((uint4*)(g_vc + ((size_t)(b * NKM + dst)) * DMODEL))[t] = z;
    }
}

// ---------------------------------------------------------------------------
// BF16 GEMM, C = A @ W^T + bias (bf16 out). 128x128 tile, BK=64, 3-stage
// cp.async, 8 warps (32x64 each), 2 CTAs/SM. Single sync per iter.
// ---------------------------------------------------------------------------
#define BM 128
#define BN 128
#define BKD 64
#define PKH 72
#define STAGEH (BM * PKH)                        // 9216 halves
#define GEMM_SMEM_BYTES (6 * STAGEH * 2)         // 110592 B
#define EPI_LD 132

struct GemmJob { const bf16* A; const bf16* W; const float* bias; bf16* C; };

__global__ __launch_bounds__(256, 2) void gemm_bf16(GemmJob j0, GemmJob j1, GemmJob j2)
{
    const GemmJob j = (blockIdx.z == 0) ? j0 : (blockIdx.z == 1 ? j1 : j2);
    extern __shared__ bf16 smh[];
    bf16* Abuf[3] = { smh, smh + 2 * STAGEH, smh + 4 * STAGEH };
    bf16* Bbuf[3] = { smh + STAGEH, smh + 3 * STAGEH, smh + 5 * STAGEH };

    const int tid  = threadIdx.x;
    const int warp = tid >> 5;
    const int wr   = warp & 3;
    const int wc   = warp >> 2;
    const int row0 = blockIdx.y * BM;
    const int col0 = blockIdx.x * BN;
    const int K = DMODEL;
    const int NIT = K / BKD;   // 16
    const int lr = tid >> 3, lc = tid & 7;

    wmma::fragment<wmma::accumulator, 16, 16, 16, float> acc[2][4];
#pragma unroll
    for (int i = 0; i < 2; i++)
#pragma unroll
        for (int c = 0; c < 4; c++) wmma::fill_fragment(acc[i][c], 0.0f);

#pragma unroll
    for (int s = 0; s < 2; s++) {
        int kb = s * BKD;
#pragma unroll
        for (int t = 0; t < 4; t++) {
            int r = lr + t * 32;
            cp16(smem_u32(&Abuf[s][r * PKH + lc * 8]), &j.A[(size_t)(row0 + r) * K + kb + lc * 8]);
            cp16(smem_u32(&Bbuf[s][r * PKH + lc * 8]), &j.W[(size_t)(col0 + r) * K + kb + lc * 8]);
        }
        cp_commit();
    }

    for (int it = 0; it < NIT; ++it) {
        if (it + 1 < NIT) cp_wait<1>(); else cp_wait<0>();
        __syncthreads();

        if (it + 2 < NIT) {
            int kb = (it + 2) * BKD;
            int st = (it + 2) % 3;
#pragma unroll
            for (int t = 0; t < 4; t++) {
                int r = lr + t * 32;
                cp16(smem_u32(&Abuf[st][r * PKH + lc * 8]), &j.A[(size_t)(row0 + r) * K + kb + lc * 8]);
                cp16(smem_u32(&Bbuf[st][r * PKH + lc * 8]), &j.W[(size_t)(col0 + r) * K + kb + lc * 8]);
            }
            cp_commit();
        }

        const bf16* Ap = Abuf[it % 3];
        const bf16* Bp = Bbuf[it % 3];
#pragma unroll
        for (int ks = 0; ks < BKD / 16; ks++) {
            wmma::fragment<wmma::matrix_a, 16, 16, 16, bf16, wmma::row_major> a0, a1;
            wmma::fragment<wmma::matrix_b, 16, 16, 16, bf16, wmma::col_major> b[4];
            wmma::load_matrix_sync(a0, &Ap[(wr * 32     ) * PKH + ks * 16], PKH);
            wmma::load_matrix_sync(a1, &Ap[(wr * 32 + 16) * PKH + ks * 16], PKH);
#pragma unroll
            for (int c = 0; c < 4; c++)
                wmma::load_matrix_sync(b[c], &Bp[(wc * 64 + c * 16) * PKH + ks * 16], PKH);
#pragma unroll
            for (int c = 0; c < 4; c++) {
                wmma::mma_sync(acc[0][c], a0, b[c], acc[0][c]);
                wmma::mma_sync(acc[1][c], a1, b[c], acc[1][c]);
            }
        }
    }
    __syncthreads();

    float (*Cs)[EPI_LD] = (float (*)[EPI_LD])smh;
#pragma unroll
    for (int i = 0; i < 2; i++)
#pragma unroll
        for (int c = 0; c < 4; c++)
            wmma::store_matrix_sync(&Cs[wr * 32 + i * 16][wc * 64 + c * 16],
                                    acc[i][c], EPI_LD, wmma::mem_row_major);
    __syncthreads();

#pragma unroll
    for (int t = 0; t < 8; t++) {
        int ch = tid + t * 256;
        int r = ch >> 4, c8 = ch & 15;
        const float* src = &Cs[r][c8 * 8];
        const float* bp  = &j.bias[col0 + c8 * 8];
        uint4 o;
        o.x = pack_bf16x2(src[0] + bp[0], src[1] + bp[1]);
        o.y = pack_bf16x2(src[2] + bp[2], src[3] + bp[3]);
        o.z = pack_bf16x2(src[4] + bp[4], src[5] + bp[5]);
        o.w = pack_bf16x2(src[6] + bp[6], src[7] + bp[7]);
        *(uint4*)&j.C[(size_t)(row0 + r) * DMODEL + col0 + c8 * 8] = o;
    }
}

// ---------------------------------------------------------------------------
// Attention on COMPACTED K/V. No masking; pad columns (zero K) contribute
// exp(0)=1 to the sum, corrected exactly by subtracting npad.
// CTA = 128 q rows x (head, batch); 8 warps, warp owns 16 rows.
// ---------------------------------------------------------------------------
#define LDQ 72
#define LDKV 72
#define ATTN_SMEM_BYTES ((128 * LDQ + 4 * 64 * LDKV) * 2)  // 55296

__global__ __launch_bounds__(256, 2) void attn_kernel()
{
    extern __shared__ char smraw[];
    bf16* Qs  = (bf16*)smraw;
    bf16* Kb0 = Qs + 128 * LDQ;
    bf16* Kb1 = Kb0 + 64 * LDKV;
    bf16* Vb0 = Kb1 + 64 * LDKV;
    bf16* Vb1 = Vb0 + 64 * LDKV;

    const int qt = blockIdx.x, h = blockIdx.y, b = blockIdx.z;
    const int tid  = threadIdx.x;
    const int warp = tid >> 5;
    const int lane = tid & 31;
    const int r = lane >> 2;
    const int c = lane & 3;
    const int lr = tid >> 3, lc8 = tid & 7;
    const int lrow8 = lane & 7;
    const int ksel  = (lane >> 3) & 1;
    const int nsel  = (lane >> 4) & 1;
    const int g  = lane >> 3;
    const int rw = lane & 7;

    const int nk = g_nk[b];
    const int KB = (nk + 127) >> 6;                 // blocks of 64 (incl. mem+pad)
    const float fpad = (float)((KB << 6) - nk - MMEM);

    const bf16* qbase = g_q + ((size_t)(b * NSEQ + qt * 128)) * DMODEL + h * DK;
    const bf16* kroot = g_kc + ((size_t)(b * NKM)) * DMODEL + h * DK;
    const bf16* vroot = g_vc + ((size_t)(b * NKM)) * DMODEL + h * DK;

    // group 0: Q
#pragma unroll
    for (int t = 0; t < 4; t++) {
        int row = lr + t * 32;
        cp16(smem_u32(&Qs[row * LDQ + lc8 * 8]), &qbase[(size_t)row * DMODEL + lc8 * 8]);
    }
    cp_commit();

    // group 1: K/V block 0
#pragma unroll
    for (int t = 0; t < 2; t++) {
        int row = lr + t * 32;
        cp16(smem_u32(&Kb0[row * LDKV + lc8 * 8]), &kroot[(size_t)row * DMODEL + lc8 * 8]);
        cp16(smem_u32(&Vb0[row * LDKV + lc8 * 8]), &vroot[(size_t)row * DMODEL + lc8 * 8]);
    }
    cp_commit();

    cp_wait<1>();          // Q complete
    __syncthreads();

    // Q fragments (A-layout, m16n8k16)
    uint32_t qf[4][4];
    {
        uint32_t q0 = smem_u32(&Qs[(warp * 16 + r) * LDQ]) + 4 * c;
        uint32_t q8 = q0 + 8 * LDQ * 2;
#pragma unroll
        for (int kc = 0; kc < 4; kc++) {
            qf[kc][0] = lds_u32(q0 + kc * 32);
            qf[kc][1] = lds_u32(q8 + kc * 32);
            qf[kc][2] = lds_u32(q0 + kc * 32 + 16);
            qf[kc][3] = lds_u32(q8 + kc * 32 + 16);
        }
    }

    float oacc[8][4];
#pragma unroll
    for (int ot = 0; ot < 8; ot++)
#pragma unroll
        for (int i = 0; i < 4; i++) oacc[ot][i] = 0.0f;
    float sum0 = 0.0f, sum1 = 0.0f;

    for (int kb = 0; kb < KB; kb++) {
        const bf16* Kp = (kb & 1) ? Kb1 : Kb0;
        const bf16* Vp = (kb & 1) ? Vb1 : Vb0;

        cp_wait<0>();
        __syncthreads();

        if (kb + 1 < KB) {
            bf16* Kn = (kb & 1) ? Kb0 : Kb1;
            bf16* Vn = (kb & 1) ? Vb0 : Vb1;
            const bf16* kp = kroot + (size_t)(kb + 1) * 64 * DMODEL;
            const bf16* vp = vroot + (size_t)(kb + 1) * 64 * DMODEL;
#pragma unroll
            for (int t = 0; t < 2; t++) {
                int row = lr + t * 32;
                cp16(smem_u32(&Kn[row * LDKV + lc8 * 8]), &kp[(size_t)row * DMODEL + lc8 * 8]);
                cp16(smem_u32(&Vn[row * LDKV + lc8 * 8]), &vp[(size_t)row * DMODEL + lc8 * 8]);
            }
            cp_commit();
        }

        // ---- S = Q @ K^T ----
        float sc[8][4];
#pragma unroll
        for (int nt = 0; nt < 8; nt++)
#pragma unroll
            for (int i = 0; i < 4; i++) sc[nt][i] = 0.0f;

        const uint32_t kfb = smem_u32(Kp) + ((nsel * 8 + lrow8) * LDKV + ksel * 8) * 2;
#pragma unroll
        for (int kc = 0; kc < 4; kc++) {
#pragma unroll
            for (int ng = 0; ng < 4; ng++) {
                uint32_t b0, b1, b2, b3;
                ldsm_x4(b0, b1, b2, b3, kfb + (ng * 16 * LDKV + kc * 16) * 2);
                mma16816(sc[2 * ng][0], sc[2 * ng][1], sc[2 * ng][2], sc[2 * ng][3],
                         qf[kc][0], qf[kc][1], qf[kc][2], qf[kc][3], b0, b1);
                mma16816(sc[2 * ng + 1][0], sc[2 * ng + 1][1], sc[2 * ng + 1][2], sc[2 * ng + 1][3],
                         qf[kc][0], qf[kc][1], qf[kc][2], qf[kc][3], b2, b3);
            }
        }

        // ---- exp (implicit max 0), pack P ----
        uint32_t pf[8][2];
#pragma unroll
        for (int nt = 0; nt < 8; nt++) {
            float p00 = __expf(sc[nt][0] * 0.125f);
            float p01 = __expf(sc[nt][1] * 0.125f);
            float p10 = __expf(sc[nt][2] * 0.125f);
            float p11 = __expf(sc[nt][3] * 0.125f);
            sum0 += p00 + p01;
            sum1 += p10 + p11;
            pf[nt][0] = pack_bf16x2(p00, p01);
            pf[nt][1] = pack_bf16x2(p10, p11);
        }

        // ---- O += P @ V ----
        const uint32_t vbase = smem_u32(Vp);
#pragma unroll
        for (int kc = 0; kc < 4; kc++) {
            uint32_t a0 = pf[2 * kc][0], a1 = pf[2 * kc][1];
            uint32_t a2 = pf[2 * kc + 1][0], a3 = pf[2 * kc + 1][1];
#pragma unroll
            for (int op = 0; op < 4; op++) {
                uint32_t addr = vbase +
                    ((16 * kc + (g & 1) * 8 + rw) * LDKV + (op * 2 + (g >> 1)) * 8) * 2;
                uint32_t b0, b1, b2, b3;
                ldsm_x4_trans(b0, b1, b2, b3, addr);
                mma16816(oacc[op * 2][0], oacc[op * 2][1], oacc[op * 2][2], oacc[op * 2][3],
                         a0, a1, a2, a3, b0, b1);
                mma16816(oacc[op * 2 + 1][0], oacc[op * 2 + 1][1],
                         oacc[op * 2 + 1][2], oacc[op * 2 + 1][3],
                         a0, a1, a2, a3, b2, b3);
            }
        }
    }

    sum0 += __shfl_xor_sync(0xffffffffu, sum0, 1);
    sum0 += __shfl_xor_sync(0xffffffffu, sum0, 2);
    sum1 += __shfl_xor_sync(0xffffffffu, sum1, 1);
    sum1 += __shfl_xor_sync(0xffffffffu, sum1, 2);
    const float inv0 = 1.0f / (sum0 - fpad);   // pad columns contributed exactly 1 each
    const float inv1 = 1.0f / (sum1 - fpad);

    bf16* ob = g_attn + ((size_t)(b * NSEQ + qt * 128 + warp * 16 + r)) * DMODEL + h * DK + 2 * c;
#pragma unroll
    for (int ot = 0; ot < 8; ot++) {
        *(uint32_t*)&ob[ot * 8] =
            pack_bf16x2(oacc[ot][0] * inv0, oacc[ot][1] * inv0);
        *(uint32_t*)&ob[8 * DMODEL + ot * 8] =
            pack_bf16x2(oacc[ot][2] * inv1, oacc[ot][3] * inv1);
    }
}

// ---------------------------------------------------------------------------
// Residual + LayerNorm. One warp per row. proj is bf16.
// ---------------------------------------------------------------------------
__global__ __launch_bounds__(256) void ln_kernel(
    const float* __restrict__ queries, const float* __restrict__ gamma,
    const float* __restrict__ beta, float* __restrict__ out)
{
    const int row  = blockIdx.x * 8 + (threadIdx.x >> 5);
    const int lane = threadIdx.x & 31;
    const float4* xin = (const float4*)(queries + (size_t)row * DMODEL);
    const uint4*  pin = (const uint4*)(g_proj + (size_t)row * DMODEL);

    float x[32];
    float s = 0.0f;
#pragma unroll
    for (int i = 0; i < 4; i++) {
        int ch = lane + i * 32;
        float4 a0 = xin[ch * 2];
        float4 a1 = xin[ch * 2 + 1];
        uint4 p = pin[ch];
        const bf162* ph = (const bf162*)&p;
        float2 p0 = __bfloat1622float2(ph[0]);
        float2 p1 = __bfloat1622float2(ph[1]);
        float2 p2 = __bfloat1622float2(ph[2]);
        float2 p3 = __bfloat1622float2(ph[3]);
        x[i * 8 + 0] = a0.x + p0.x; x[i * 8 + 1] = a0.y + p0.y;
        x[i * 8 + 2] = a0.z + p1.x; x[i * 8 + 3] = a0.w + p1.y;
        x[i * 8 + 4] = a1.x + p2.x; x[i * 8 + 5] = a1.y + p2.y;
        x[i * 8 + 6] = a1.z + p3.x; x[i * 8 + 7] = a1.w + p3.y;
#pragma unroll
        for (int k = 0; k < 8; k++) s += x[i * 8 + k];
    }
#pragma unroll
    for (int o = 16; o; o >>= 1) s += __shfl_xor_sync(0xffffffffu, s, o);
    const float mu = s * (1.0f / DMODEL);

    float v = 0.0f;
#pragma unroll
    for (int i = 0; i < 32; i++) { float d = x[i] - mu; v += d * d; }
#pragma unroll
    for (int o = 16; o; o >>= 1) v += __shfl_xor_sync(0xffffffffu, v, o);
    const float rs = rsqrtf(v * (1.0f / DMODEL) + EPS);

    float4* op = (float4*)(out + (size_t)row * DMODEL);
    const float4* gp = (const float4*)gamma;
    const float4* bp = (const float4*)beta;
#pragma unroll
    for (int i = 0; i < 4; i++) {
        int ch = lane + i * 32;
#pragma unroll
        for (int half = 0; half < 2; half++) {
            float4 g  = gp[ch * 2 + half];
            float4 be = bp[ch * 2 + half];
            float4 o4;
            o4.x = (x[i * 8 + half * 4 + 0] - mu) * rs * g.x + be.x;
            o4.y = (x[i * 8 + half * 4 + 1] - mu) * rs * g.y + be.y;
            o4.z = (x[i * 8 + half * 4 + 2] - mu) * rs * g.z + be.z;
            o4.w = (x[i * 8 + half * 4 + 3] - mu) * rs * g.w + be.w;
            op[ch * 2 + half] = o4;
        }
    }
}

// ---------------------------------------------------------------------------
// Launch
// ---------------------------------------------------------------------------
extern "C" void kernel_launch(void* const* d_in, const int* in_sizes, int n_in,
                              void* d_out, int out_size)
{
    const float* queries = (const float*)d_in[0];
    const float* keys    = (const float*)d_in[1];
    const float* values  = (const float*)d_in[2];
    const int*   amask   = (const int*)  d_in[3];
    const float* Wq = (const float*)d_in[4],  *bq = (const float*)d_in[5];
    const float* Wk = (const float*)d_in[6],  *bk = (const float*)d_in[7];
    const float* Wv = (const float*)d_in[8],  *bv = (const float*)d_in[9];
    const float* Wo = (const float*)d_in[10], *bo = (const float*)d_in[11];
    const float* m_k = (const float*)d_in[12], *m_v = (const float*)d_in[13];
    const float* gamma = (const float*)d_in[14], *beta = (const float*)d_in[15];
    float* out = (float*)d_out;

    bf16 *xq, *xk, *xv, *wq, *wk, *wv, *wo, *pq, *pk, *pv, *pa, *pp;
    cudaGetSymbolAddress((void**)&xq, g_xq);
    cudaGetSymbolAddress((void**)&xk, g_xk);
    cudaGetSymbolAddress((void**)&xv, g_xv);
    cudaGetSymbolAddress((void**)&wq, g_wq);
    cudaGetSymbolAddress((void**)&wk, g_wk);
    cudaGetSymbolAddress((void**)&wv, g_wv);
    cudaGetSymbolAddress((void**)&wo, g_wo);
    cudaGetSymbolAddress((void**)&pq, g_q);
    cudaGetSymbolAddress((void**)&pk, g_k);
    cudaGetSymbolAddress((void**)&pv, g_v);
    cudaGetSymbolAddress((void**)&pa, g_attn);
    cudaGetSymbolAddress((void**)&pp, g_proj);

    cudaFuncSetAttribute(gemm_bf16,
                         cudaFuncAttributeMaxDynamicSharedMemorySize, GEMM_SMEM_BYTES);
    cudaFuncSetAttribute(attn_kernel,
                         cudaFuncAttributeMaxDynamicSharedMemorySize, ATTN_SMEM_BYTES);

    const int Mrows = BATCH * NSEQ;        // 4096
    const int NACT  = Mrows * DMODEL;      // 4M
    const int NWEI  = DMODEL * DMODEL;     // 1M

    CvtJob cj0 = { queries, xq, NACT };
    CvtJob cj1 = { keys,    xk, NACT };
    CvtJob cj2 = { values,  xv, NACT };
    CvtJob cj3 = { Wq, wq, NWEI };
    CvtJob cj4 = { Wk, wk, NWEI };
    CvtJob cj5 = { Wv, wv, NWEI };
    CvtJob cj6 = { Wo, wo, NWEI };
    cvt_all<<<dim3(NACT / 2048, 7), 256>>>(cj0, cj1, cj2, cj3, cj4, cj5, cj6);

    // mask scan (independent of GEMM inputs)
    mask_scan<<<BATCH, 1024>>>(amask);

    GemmJob jq = { xq, wq, bq, pq };
    GemmJob jk = { xk, wk, bk, pk };
    GemmJob jv = { xv, wv, bv, pv };
    GemmJob jo = { pa, wo, bo, pp };

    // fused Q/K/V projections
    dim3 g3(DMODEL / BN, Mrows / BM, 3);   // (8, 32, 3)
    gemm_bf16<<<g3, 256, GEMM_SMEM_BYTES>>>(jq, jk, jv);

    // compact K/V (survivors + memory rows + zero pad)
    compact_kv<<<dim3(NSEQ + MMEM + 64, BATCH), 128>>>(m_k, m_v);

    // attention over compacted keys
    attn_kernel<<<dim3(NSEQ / 128, NHEAD, BATCH), 256, ATTN_SMEM_BYTES>>>();

    // output projection
    dim3 g1(DMODEL / BN, Mrows / BM, 1);
    gemm_bf16<<<g1, 256, GEMM_SMEM_BYTES>>>(jo, jo, jo);

    ln_kernel<<<Mrows / 8, 256>>>(queries, gamma, beta, out);
}

// round 11
// speedup vs baseline: 1.5664x; 1.2313x over previous
#include <cuda_runtime.h>
#include <cuda_bf16.h>
#include <mma.h>
#include <cstdint>

using namespace nvcuda;

// ---------------------------------------------------------------------------
// Problem constants
// ---------------------------------------------------------------------------
#define BATCH 4
#define NSEQ  1024
#define DMODEL 1024
#define NHEAD 16
#define DK 64
#define MMEM 64
#define NKM (NSEQ + MMEM)   // 1088
#define EPS 1e-5f

typedef __nv_bfloat16  bf16;
typedef __nv_bfloat162 bf162;

// ---------------------------------------------------------------------------
// Scratch
// ---------------------------------------------------------------------------
__device__ bf16  g_xq [BATCH * NSEQ * DMODEL];
__device__ bf16  g_xkc[BATCH * NKM  * DMODEL];    // compacted bf16 input keys
__device__ bf16  g_xvc[BATCH * NKM  * DMODEL];    // compacted bf16 input values
__device__ bf16  g_wq[DMODEL * DMODEL];
__device__ bf16  g_wk[DMODEL * DMODEL];
__device__ bf16  g_wv[DMODEL * DMODEL];
__device__ bf16  g_wo[DMODEL * DMODEL];
__device__ bf16  g_q   [BATCH * NSEQ * DMODEL];
__device__ bf16  g_kc  [BATCH * NKM  * DMODEL];   // projected compacted K (+mem,+pad)
__device__ bf16  g_vc  [BATCH * NKM  * DMODEL];
__device__ bf16  g_attn[BATCH * NSEQ * DMODEL];
__device__ bf16  g_proj[BATCH * NSEQ * DMODEL];
__device__ int   g_pos [BATCH * NSEQ];            // compaction target (-1 = masked)
__device__ int   g_nk  [BATCH];                   // survivors per batch

// ---------------------------------------------------------------------------
// helpers
// ---------------------------------------------------------------------------
__device__ __forceinline__ uint32_t smem_u32(const void* p) {
    return (uint32_t)__cvta_generic_to_shared(p);
}
__device__ __forceinline__ void cp16(uint32_t dst, const void* src) {
    asm volatile("cp.async.cg.shared.global [%0], [%1], 16;" :: "r"(dst), "l"(src));
}
__device__ __forceinline__ void cp_commit() {
    asm volatile("cp.async.commit_group;");
}
template<int N> __device__ __forceinline__ void cp_wait() {
    asm volatile("cp.async.wait_group %0;" :: "n"(N));
}
__device__ __forceinline__ uint32_t lds_u32(uint32_t a) {
    uint32_t v;
    asm volatile("ld.shared.b32 %0, [%1];" : "=r"(v) : "r"(a));
    return v;
}
__device__ __forceinline__ void ldsm_x4(uint32_t& d0, uint32_t& d1,
                                        uint32_t& d2, uint32_t& d3, uint32_t a) {
    asm volatile("ldmatrix.sync.aligned.m8n8.x4.shared.b16 {%0,%1,%2,%3}, [%4];"
                 : "=r"(d0), "=r"(d1), "=r"(d2), "=r"(d3) : "r"(a));
}
__device__ __forceinline__ void ldsm_x4_trans(uint32_t& d0, uint32_t& d1,
                                              uint32_t& d2, uint32_t& d3, uint32_t a) {
    asm volatile("ldmatrix.sync.aligned.m8n8.x4.trans.shared.b16 {%0,%1,%2,%3}, [%4];"
                 : "=r"(d0), "=r"(d1), "=r"(d2), "=r"(d3) : "r"(a));
}
__device__ __forceinline__ void mma16816(float& c0, float& c1, float& c2, float& c3,
                                         uint32_t a0, uint32_t a1, uint32_t a2, uint32_t a3,
                                         uint32_t b0, uint32_t b1) {
    asm volatile("mma.sync.aligned.m16n8k16.row.col.f32.bf16.bf16.f32 "
                 "{%0,%1,%2,%3}, {%4,%5,%6,%7}, {%8,%9}, {%0,%1,%2,%3};"
                 : "+f"(c0), "+f"(c1), "+f"(c2), "+f"(c3)
                 : "r"(a0), "r"(a1), "r"(a2), "r"(a3), "r"(b0), "r"(b1));
}
__device__ __forceinline__ uint32_t pack_bf16x2(float lo, float hi) {
    bf162 t = __floats2bfloat162_rn(lo, hi);
    return *(uint32_t*)&t;
}

// ---------------------------------------------------------------------------
// fp32 -> bf16 conversion, 5 tensors in one launch (grid.y = job).
// ---------------------------------------------------------------------------
struct CvtJob { const float* in; bf16* out; int n; };

__global__ __launch_bounds__(256) void cvt_all(
    CvtJob j0, CvtJob j1, CvtJob j2, CvtJob j3, CvtJob j4)
{
    CvtJob j;
    switch (blockIdx.y) {
        case 0: j = j0; break; case 1: j = j1; break; case 2: j = j2; break;
        case 3: j = j3; break; default: j = j4; break;
    }
    int i = (blockIdx.x * 256 + threadIdx.x) * 8;
    if (i >= j.n) return;
    float4 v0 = *(const float4*)(j.in + i);
    float4 v1 = *(const float4*)(j.in + i + 4);
    uint4 o;
    o.x = pack_bf16x2(v0.x, v0.y); o.y = pack_bf16x2(v0.z, v0.w);
    o.z = pack_bf16x2(v1.x, v1.y); o.w = pack_bf16x2(v1.z, v1.w);
    *(uint4*)(j.out + i) = o;
}

// ---------------------------------------------------------------------------
// Mask scan: per batch, exclusive prefix positions of unmasked columns.
// ---------------------------------------------------------------------------
__global__ __launch_bounds__(1024) void mask_scan(const int* __restrict__ amask)
{
    const int b = blockIdx.x;
    const int i = threadIdx.x;
    const int lane = i & 31, w = i >> 5;
    int keep = (amask[b * NSEQ + i] == 0) ? 1 : 0;
    unsigned bal = __ballot_sync(0xffffffffu, keep);
    int before = __popc(bal & ((1u << lane) - 1));
    __shared__ int wsum[32];
    if (lane == 0) wsum[w] = __popc(bal);
    __syncthreads();
    if (w == 0) {
        int v = wsum[lane];
#pragma unroll
        for (int o = 1; o < 32; o <<= 1) {
            int t = __shfl_up_sync(0xffffffffu, v, o);
            if (lane >= o) v += t;
        }
        wsum[lane] = v;
    }
    __syncthreads();
    int base = (w == 0) ? 0 : wsum[w - 1];
    g_pos[b * NSEQ + i] = keep ? (base + before) : -1;
    if (i == 1023) g_nk[b] = wsum[31];
}

// ---------------------------------------------------------------------------
// Compact INPUT keys/values (fp32) -> bf16 rows at compacted positions.
// One block (128 threads) per source row; 8 floats per thread.
// ---------------------------------------------------------------------------
__global__ __launch_bounds__(128) void compact_in(
    const float* __restrict__ keys, const float* __restrict__ values)
{
    const int b = blockIdx.y;
    const int x = blockIdx.x;
    const int t = threadIdx.x;
    int pos = g_pos[b * NSEQ + x];
    if (pos < 0) return;
    const float4* ks = (const float4*)(keys   + ((size_t)(b * NSEQ + x)) * DMODEL);
    const float4* vs = (const float4*)(values + ((size_t)(b * NSEQ + x)) * DMODEL);
    float4 k0 = ks[t * 2], k1 = ks[t * 2 + 1];
    float4 v0 = vs[t * 2], v1 = vs[t * 2 + 1];
    uint4 ko, vo;
    ko.x = pack_bf16x2(k0.x, k0.y); ko.y = pack_bf16x2(k0.z, k0.w);
    ko.z = pack_bf16x2(k1.x, k1.y); ko.w = pack_bf16x2(k1.z, k1.w);
    vo.x = pack_bf16x2(v0.x, v0.y); vo.y = pack_bf16x2(v0.z, v0.w);
    vo.z = pack_bf16x2(v1.x, v1.y); vo.w = pack_bf16x2(v1.z, v1.w);
    ((uint4*)(g_xkc + ((size_t)(b * NKM + pos)) * DMODEL))[t] = ko;
    ((uint4*)(g_xvc + ((size_t)(b * NKM + pos)) * DMODEL))[t] = vo;
}

// ---------------------------------------------------------------------------
// Finish compacted K/V: write memory rows (x8) at [nk, nk+64) and zero pad
// rows up to the next 64 multiple. Runs AFTER the K/V projection so it
// overwrites any garbage the projection wrote past nk.
// ---------------------------------------------------------------------------
__global__ __launch_bounds__(128) void kv_finish(
    const float* __restrict__ m_k, const float* __restrict__ m_v)
{
    const int b = blockIdx.y;
    const int x = blockIdx.x;      // 0..MMEM+63
    const int t = threadIdx.x;
    const int nk = g_nk[b];

    if (x < MMEM) {
        int dst = nk + x;
        const float4* mk = (const float4*)(m_k + (size_t)x * DMODEL);
        const float4* mv = (const float4*)(m_v + (size_t)x * DMODEL);
        float4 a0 = mk[t * 2], a1 = mk[t * 2 + 1];
        float4 b0 = mv[t * 2], b1 = mv[t * 2 + 1];
        uint4 ko, vo;
        ko.x = pack_bf16x2(a0.x * 8.f, a0.y * 8.f); ko.y = pack_bf16x2(a0.z * 8.f, a0.w * 8.f);
        ko.z = pack_bf16x2(a1.x * 8.f, a1.y * 8.f); ko.w = pack_bf16x2(a1.z * 8.f, a1.w * 8.f);
        vo.x = pack_bf16x2(b0.x * 8.f, b0.y * 8.f); vo.y = pack_bf16x2(b0.z * 8.f, b0.w * 8.f);
        vo.z = pack_bf16x2(b1.x * 8.f, b1.y * 8.f); vo.w = pack_bf16x2(b1.z * 8.f, b1.w * 8.f);
        ((uint4*)(g_kc + ((size_t)(b * NKM + dst)) * DMODEL))[t] = ko;
        ((uint4*)(g_vc + ((size_t)(b * NKM + dst)) * DMODEL))[t] = vo;
    } else {
        int p = x - MMEM;
        int dst = nk + MMEM + p;
        int KB = (nk + 127) >> 6;
        if (dst >= (KB << 6)) return;
        uint4 z = {0, 0, 0, 0};
        ((uint4*)(g_kc + ((size_t)(b * NKM + dst)) * DMODEL))[t] = z;
        ((uint4*)(g_vc + ((size_t)(b * NKM + dst)) * DMODEL))[t] = z;
    }
}

// ---------------------------------------------------------------------------
// BF16 GEMM, C = A @ W^T + bias (bf16 out). 128x128 tile, BK=64, 3-stage
// cp.async, 8 warps (32x64 each), 2 CTAs/SM. Dense variant (Q / Wo).
// ---------------------------------------------------------------------------
#define BM 128
#define BN 128
#define BKD 64
#define PKH 72
#define STAGEH (BM * PKH)                        // 9216 halves
#define GEMM_SMEM_BYTES (6 * STAGEH * 2)         // 110592 B
#define EPI_LD 132

struct GemmJob { const bf16* A; const bf16* W; const float* bias; bf16* C; };

// Shared GEMM body: computes the 128x128 tile at (arow0 in A/C row space, col0).
__device__ __forceinline__ void gemm_tile(
    const bf16* __restrict__ A, const bf16* __restrict__ W,
    const float* __restrict__ bias, bf16* __restrict__ C,
    size_t arow0, int col0, bf16* smh)
{
    bf16* Abuf[3] = { smh, smh + 2 * STAGEH, smh + 4 * STAGEH };
    bf16* Bbuf[3] = { smh + STAGEH, smh + 3 * STAGEH, smh + 5 * STAGEH };

    const int tid  = threadIdx.x;
    const int warp = tid >> 5;
    const int wr   = warp & 3;
    const int wc   = warp >> 2;
    const int K = DMODEL;
    const int NIT = K / BKD;   // 16
    const int lr = tid >> 3, lc = tid & 7;

    wmma::fragment<wmma::accumulator, 16, 16, 16, float> acc[2][4];
#pragma unroll
    for (int i = 0; i < 2; i++)
#pragma unroll
        for (int c = 0; c < 4; c++) wmma::fill_fragment(acc[i][c], 0.0f);

#pragma unroll
    for (int s = 0; s < 2; s++) {
        int kb = s * BKD;
#pragma unroll
        for (int t = 0; t < 4; t++) {
            int r = lr + t * 32;
            cp16(smem_u32(&Abuf[s][r * PKH + lc * 8]), &A[(arow0 + r) * K + kb + lc * 8]);
            cp16(smem_u32(&Bbuf[s][r * PKH + lc * 8]), &W[(size_t)(col0 + r) * K + kb + lc * 8]);
        }
        cp_commit();
    }

    for (int it = 0; it < NIT; ++it) {
        if (it + 1 < NIT) cp_wait<1>(); else cp_wait<0>();
        __syncthreads();

        if (it + 2 < NIT) {
            int kb = (it + 2) * BKD;
            int st = (it + 2) % 3;
#pragma unroll
            for (int t = 0; t < 4; t++) {
                int r = lr + t * 32;
                cp16(smem_u32(&Abuf[st][r * PKH + lc * 8]), &A[(arow0 + r) * K + kb + lc * 8]);
                cp16(smem_u32(&Bbuf[st][r * PKH + lc * 8]), &W[(size_t)(col0 + r) * K + kb + lc * 8]);
            }
            cp_commit();
        }

        const bf16* Ap = Abuf[it % 3];
        const bf16* Bp = Bbuf[it % 3];
#pragma unroll
        for (int ks = 0; ks < BKD / 16; ks++) {
            wmma::fragment<wmma::matrix_a, 16, 16, 16, bf16, wmma::row_major> a0, a1;
            wmma::fragment<wmma::matrix_b, 16, 16, 16, bf16, wmma::col_major> b[4];
            wmma::load_matrix_sync(a0, &Ap[(wr * 32     ) * PKH + ks * 16], PKH);
            wmma::load_matrix_sync(a1, &Ap[(wr * 32 + 16) * PKH + ks * 16], PKH);
#pragma unroll
            for (int c = 0; c < 4; c++)
                wmma::load_matrix_sync(b[c], &Bp[(wc * 64 + c * 16) * PKH + ks * 16], PKH);
#pragma unroll
            for (int c = 0; c < 4; c++) {
                wmma::mma_sync(acc[0][c], a0, b[c], acc[0][c]);
                wmma::mma_sync(acc[1][c], a1, b[c], acc[1][c]);
            }
        }
    }
    __syncthreads();

    float (*Cs)[EPI_LD] = (float (*)[EPI_LD])smh;
#pragma unroll
    for (int i = 0; i < 2; i++)
#pragma unroll
        for (int c = 0; c < 4; c++)
            wmma::store_matrix_sync(&Cs[wr * 32 + i * 16][wc * 64 + c * 16],
                                    acc[i][c], EPI_LD, wmma::mem_row_major);
    __syncthreads();

#pragma unroll
    for (int t = 0; t < 8; t++) {
        int ch = tid + t * 256;
        int r = ch >> 4, c8 = ch & 15;
        const float* src = &Cs[r][c8 * 8];
        const float* bp  = &bias[col0 + c8 * 8];
        uint4 o;
        o.x = pack_bf16x2(src[0] + bp[0], src[1] + bp[1]);
        o.y = pack_bf16x2(src[2] + bp[2], src[3] + bp[3]);
        o.z = pack_bf16x2(src[4] + bp[4], src[5] + bp[5]);
        o.w = pack_bf16x2(src[6] + bp[6], src[7] + bp[7]);
        *(uint4*)&C[(arow0 + r) * DMODEL + col0 + c8 * 8] = o;
    }
}

__global__ __launch_bounds__(256, 2) void gemm_bf16(GemmJob j0, GemmJob j1)
{
    const GemmJob j = (blockIdx.z == 0) ? j0 : j1;
    extern __shared__ bf16 smh[];
    gemm_tile(j.A, j.W, j.bias, j.C,
              (size_t)blockIdx.y * BM, blockIdx.x * BN, smh);
}

// K/V projection on compacted rows. grid.y encodes (batch, row-tile);
// tiles past the padded survivor count exit immediately.
__global__ __launch_bounds__(256, 2) void gemm_kv(
    const bf16* W0, const bf16* W1, const float* b0_, const float* b1_)
{
    const int b  = blockIdx.y >> 3;
    const int rt = blockIdx.y & 7;
    const int nkpad = (g_nk[b] + 127) & ~127;
    if (rt * BM >= nkpad) return;
    extern __shared__ bf16 smh[];
    const bf16* A = blockIdx.z ? g_xvc : g_xkc;
    const bf16* W = blockIdx.z ? W1 : W0;
    const float* bias = blockIdx.z ? b1_ : b0_;
    bf16* C = blockIdx.z ? g_vc : g_kc;
    gemm_tile(A, W, bias, C,
              (size_t)b * NKM + rt * BM, blockIdx.x * BN, smh);
}

// ---------------------------------------------------------------------------
// Attention on COMPACTED K/V. No masking; pad columns (zero K) contribute
// exp(0)=1 to the sum, corrected exactly by subtracting npad.
// ---------------------------------------------------------------------------
#define LDQ 72
#define LDKV 72
#define ATTN_SMEM_BYTES ((128 * LDQ + 4 * 64 * LDKV) * 2)  // 55296

__global__ __launch_bounds__(256, 2) void attn_kernel()
{
    extern __shared__ char smraw[];
    bf16* Qs  = (bf16*)smraw;
    bf16* Kb0 = Qs + 128 * LDQ;
    bf16* Kb1 = Kb0 + 64 * LDKV;
    bf16* Vb0 = Kb1 + 64 * LDKV;
    bf16* Vb1 = Vb0 + 64 * LDKV;

    const int qt = blockIdx.x, h = blockIdx.y, b = blockIdx.z;
    const int tid  = threadIdx.x;
    const int warp = tid >> 5;
    const int lane = tid & 31;
    const int r = lane >> 2;
    const int c = lane & 3;
    const int lr = tid >> 3, lc8 = tid & 7;
    const int lrow8 = lane & 7;
    const int ksel  = (lane >> 3) & 1;
    const int nsel  = (lane >> 4) & 1;
    const int g  = lane >> 3;
    const int rw = lane & 7;

    const int nk = g_nk[b];
    const int KB = (nk + 127) >> 6;
    const float fpad = (float)((KB << 6) - nk - MMEM);

    const bf16* qbase = g_q + ((size_t)(b * NSEQ + qt * 128)) * DMODEL + h * DK;
    const bf16* kroot = g_kc + ((size_t)(b * NKM)) * DMODEL + h * DK;
    const bf16* vroot = g_vc + ((size_t)(b * NKM)) * DMODEL + h * DK;

#pragma unroll
    for (int t = 0; t < 4; t++) {
        int row = lr + t * 32;
        cp16(smem_u32(&Qs[row * LDQ + lc8 * 8]), &qbase[(size_t)row * DMODEL + lc8 * 8]);
    }
    cp_commit();

#pragma unroll
    for (int t = 0; t < 2; t++) {
        int row = lr + t * 32;
        cp16(smem_u32(&Kb0[row * LDKV + lc8 * 8]), &kroot[(size_t)row * DMODEL + lc8 * 8]);
        cp16(smem_u32(&Vb0[row * LDKV + lc8 * 8]), &vroot[(size_t)row * DMODEL + lc8 * 8]);
    }
    cp_commit();

    cp_wait<1>();
    __syncthreads();

    uint32_t qf[4][4];
    {
        uint32_t q0 = smem_u32(&Qs[(warp * 16 + r) * LDQ]) + 4 * c;
        uint32_t q8 = q0 + 8 * LDQ * 2;
#pragma unroll
        for (int kc = 0; kc < 4; kc++) {
            qf[kc][0] = lds_u32(q0 + kc * 32);
            qf[kc][1] = lds_u32(q8 + kc * 32);
            qf[kc][2] = lds_u32(q0 + kc * 32 + 16);
            qf[kc][3] = lds_u32(q8 + kc * 32 + 16);
        }
    }

    float oacc[8][4];
#pragma unroll
    for (int ot = 0; ot < 8; ot++)
#pragma unroll
        for (int i = 0; i < 4; i++) oacc[ot][i] = 0.0f;
    float sum0 = 0.0f, sum1 = 0.0f;

    for (int kb = 0; kb < KB; kb++) {
        const bf16* Kp = (kb & 1) ? Kb1 : Kb0;
        const bf16* Vp = (kb & 1) ? Vb1 : Vb0;

        cp_wait<0>();
        __syncthreads();

        if (kb + 1 < KB) {
            bf16* Kn = (kb & 1) ? Kb0 : Kb1;
            bf16* Vn = (kb & 1) ? Vb0 : Vb1;
            const bf16* kp = kroot + (size_t)(kb + 1) * 64 * DMODEL;
            const bf16* vp = vroot + (size_t)(kb + 1) * 64 * DMODEL;
#pragma unroll
            for (int t = 0; t < 2; t++) {
                int row = lr + t * 32;
                cp16(smem_u32(&Kn[row * LDKV + lc8 * 8]), &kp[(size_t)row * DMODEL + lc8 * 8]);
                cp16(smem_u32(&Vn[row * LDKV + lc8 * 8]), &vp[(size_t)row * DMODEL + lc8 * 8]);
            }
            cp_commit();
        }

        float sc[8][4];
#pragma unroll
        for (int nt = 0; nt < 8; nt++)
#pragma unroll
            for (int i = 0; i < 4; i++) sc[nt][i] = 0.0f;

        const uint32_t kfb = smem_u32(Kp) + ((nsel * 8 + lrow8) * LDKV + ksel * 8) * 2;
#pragma unroll
        for (int kc = 0; kc < 4; kc++) {
#pragma unroll
            for (int ng = 0; ng < 4; ng++) {
                uint32_t b0, b1, b2, b3;
                ldsm_x4(b0, b1, b2, b3, kfb + (ng * 16 * LDKV + kc * 16) * 2);
                mma16816(sc[2 * ng][0], sc[2 * ng][1], sc[2 * ng][2], sc[2 * ng][3],
                         qf[kc][0], qf[kc][1], qf[kc][2], qf[kc][3], b0, b1);
                mma16816(sc[2 * ng + 1][0], sc[2 * ng + 1][1], sc[2 * ng + 1][2], sc[2 * ng + 1][3],
                         qf[kc][0], qf[kc][1], qf[kc][2], qf[kc][3], b2, b3);
            }
        }

        uint32_t pf[8][2];
#pragma unroll
        for (int nt = 0; nt < 8; nt++) {
            float p00 = __expf(sc[nt][0] * 0.125f);
            float p01 = __expf(sc[nt][1] * 0.125f);
            float p10 = __expf(sc[nt][2] * 0.125f);
            float p11 = __expf(sc[nt][3] * 0.125f);
            sum0 += p00 + p01;
            sum1 += p10 + p11;
            pf[nt][0] = pack_bf16x2(p00, p01);
            pf[nt][1] = pack_bf16x2(p10, p11);
        }

        const uint32_t vbase = smem_u32(Vp);
#pragma unroll
        for (int kc = 0; kc < 4; kc++) {
            uint32_t a0 = pf[2 * kc][0], a1 = pf[2 * kc][1];
            uint32_t a2 = pf[2 * kc + 1][0], a3 = pf[2 * kc + 1][1];
#pragma unroll
            for (int op = 0; op < 4; op++) {
                uint32_t addr = vbase +
                    ((16 * kc + (g & 1) * 8 + rw) * LDKV + (op * 2 + (g >> 1)) * 8) * 2;
                uint32_t b0, b1, b2, b3;
                ldsm_x4_trans(b0, b1, b2, b3, addr);
                mma16816(oacc[op * 2][0], oacc[op * 2][1], oacc[op * 2][2], oacc[op * 2][3],
                         a0, a1, a2, a3, b0, b1);
                mma16816(oacc[op * 2 + 1][0], oacc[op * 2 + 1][1],
                         oacc[op * 2 + 1][2], oacc[op * 2 + 1][3],
                         a0, a1, a2, a3, b2, b3);
            }
        }
    }

    sum0 += __shfl_xor_sync(0xffffffffu, sum0, 1);
    sum0 += __shfl_xor_sync(0xffffffffu, sum0, 2);
    sum1 += __shfl_xor_sync(0xffffffffu, sum1, 1);
    sum1 += __shfl_xor_sync(0xffffffffu, sum1, 2);
    const float inv0 = 1.0f / (sum0 - fpad);
    const float inv1 = 1.0f / (sum1 - fpad);

    bf16* ob = g_attn + ((size_t)(b * NSEQ + qt * 128 + warp * 16 + r)) * DMODEL + h * DK + 2 * c;
#pragma unroll
    for (int ot = 0; ot < 8; ot++) {
        *(uint32_t*)&ob[ot * 8] =
            pack_bf16x2(oacc[ot][0] * inv0, oacc[ot][1] * inv0);
        *(uint32_t*)&ob[8 * DMODEL + ot * 8] =
            pack_bf16x2(oacc[ot][2] * inv1, oacc[ot][3] * inv1);
    }
}

// ---------------------------------------------------------------------------
// Residual + LayerNorm. One warp per row. proj is bf16.
// ---------------------------------------------------------------------------
__global__ __launch_bounds__(256) void ln_kernel(
    const float* __restrict__ queries, const float* __restrict__ gamma,
    const float* __restrict__ beta, float* __restrict__ out)
{
    const int row  = blockIdx.x * 8 + (threadIdx.x >> 5);
    const int lane = threadIdx.x & 31;
    const float4* xin = (const float4*)(queries + (size_t)row * DMODEL);
    const uint4*  pin = (const uint4*)(g_proj + (size_t)row * DMODEL);

    float x[32];
    float s = 0.0f;
#pragma unroll
    for (int i = 0; i < 4; i++) {
        int ch = lane + i * 32;
        float4 a0 = xin[ch * 2];
        float4 a1 = xin[ch * 2 + 1];
        uint4 p = pin[ch];
        const bf162* ph = (const bf162*)&p;
        float2 p0 = __bfloat1622float2(ph[0]);
        float2 p1 = __bfloat1622float2(ph[1]);
        float2 p2 = __bfloat1622float2(ph[2]);
        float2 p3 = __bfloat1622float2(ph[3]);
        x[i * 8 + 0] = a0.x + p0.x; x[i * 8 + 1] = a0.y + p0.y;
        x[i * 8 + 2] = a0.z + p1.x; x[i * 8 + 3] = a0.w + p1.y;
        x[i * 8 + 4] = a1.x + p2.x; x[i * 8 + 5] = a1.y + p2.y;
        x[i * 8 + 6] = a1.z + p3.x; x[i * 8 + 7] = a1.w + p3.y;
#pragma unroll
        for (int k = 0; k < 8; k++) s += x[i * 8 + k];
    }
#pragma unroll
    for (int o = 16; o; o >>= 1) s += __shfl_xor_sync(0xffffffffu, s, o);
    const float mu = s * (1.0f / DMODEL);

    float v = 0.0f;
#pragma unroll
    for (int i = 0; i < 32; i++) { float d = x[i] - mu; v += d * d; }
#pragma unroll
    for (int o = 16; o; o >>= 1) v += __shfl_xor_sync(0xffffffffu, v, o);
    const float rs = rsqrtf(v * (1.0f / DMODEL) + EPS);

    float4* op = (float4*)(out + (size_t)row * DMODEL);
    const float4* gp = (const float4*)gamma;
    const float4* bp = (const float4*)beta;
#pragma unroll
    for (int i = 0; i < 4; i++) {
        int ch = lane + i * 32;
#pragma unroll
        for (int half = 0; half < 2; half++) {
            float4 g  = gp[ch * 2 + half];
            float4 be = bp[ch * 2 + half];
            float4 o4;
            o4.x = (x[i * 8 + half * 4 + 0] - mu) * rs * g.x + be.x;
            o4.y = (x[i * 8 + half * 4 + 1] - mu) * rs * g.y + be.y;
            o4.z = (x[i * 8 + half * 4 + 2] - mu) * rs * g.z + be.z;
            o4.w = (x[i * 8 + half * 4 + 3] - mu) * rs * g.w + be.w;
            op[ch * 2 + half] = o4;
        }
    }
}

// ---------------------------------------------------------------------------
// Launch
// ---------------------------------------------------------------------------
extern "C" void kernel_launch(void* const* d_in, const int* in_sizes, int n_in,
                              void* d_out, int out_size)
{
    const float* queries = (const float*)d_in[0];
    const float* keys    = (const float*)d_in[1];
    const float* values  = (const float*)d_in[2];
    const int*   amask   = (const int*)  d_in[3];
    const float* Wq = (const float*)d_in[4],  *bq = (const float*)d_in[5];
    const float* Wk = (const float*)d_in[6],  *bk = (const float*)d_in[7];
    const float* Wv = (const float*)d_in[8],  *bv = (const float*)d_in[9];
    const float* Wo = (const float*)d_in[10], *bo = (const float*)d_in[11];
    const float* m_k = (const float*)d_in[12], *m_v = (const float*)d_in[13];
    const float* gamma = (const float*)d_in[14], *beta = (const float*)d_in[15];
    float* out = (float*)d_out;

    bf16 *xq, *wq, *wk, *wv, *wo, *pq, *pa, *pp;
    cudaGetSymbolAddress((void**)&xq, g_xq);
    cudaGetSymbolAddress((void**)&wq, g_wq);
    cudaGetSymbolAddress((void**)&wk, g_wk);
    cudaGetSymbolAddress((void**)&wv, g_wv);
    cudaGetSymbolAddress((void**)&wo, g_wo);
    cudaGetSymbolAddress((void**)&pq, g_q);
    cudaGetSymbolAddress((void**)&pa, g_attn);
    cudaGetSymbolAddress((void**)&pp, g_proj);

    cudaFuncSetAttribute(gemm_bf16,
                         cudaFuncAttributeMaxDynamicSharedMemorySize, GEMM_SMEM_BYTES);
    cudaFuncSetAttribute(gemm_kv,
                         cudaFuncAttributeMaxDynamicSharedMemorySize, GEMM_SMEM_BYTES);
    cudaFuncSetAttribute(attn_kernel,
                         cudaFuncAttributeMaxDynamicSharedMemorySize, ATTN_SMEM_BYTES);

    const int Mrows = BATCH * NSEQ;        // 4096
    const int NACT  = Mrows * DMODEL;      // 4M
    const int NWEI  = DMODEL * DMODEL;     // 1M

    CvtJob cj0 = { queries, xq, NACT };
    CvtJob cj1 = { Wq, wq, NWEI };
    CvtJob cj2 = { Wk, wk, NWEI };
    CvtJob cj3 = { Wv, wv, NWEI };
    CvtJob cj4 = { Wo, wo, NWEI };
    cvt_all<<<dim3(NACT / 2048, 5), 256>>>(cj0, cj1, cj2, cj3, cj4);

    mask_scan<<<BATCH, 1024>>>(amask);

    // compact input keys/values to survivor rows (bf16)
    compact_in<<<dim3(NSEQ, BATCH), 128>>>(keys, values);

    // Q projection (dense, 256 tiles)
    GemmJob jq = { xq, wq, bq, pq };
    gemm_bf16<<<dim3(DMODEL / BN, Mrows / BM, 1), 256, GEMM_SMEM_BYTES>>>(jq, jq);

    // K/V projection on compacted rows (early-exit past survivor count)
    gemm_kv<<<dim3(DMODEL / BN, 8 * BATCH, 2), 256, GEMM_SMEM_BYTES>>>(wk, wv, bk, bv);

    // memory rows + zero pad (overwrites projection garbage past nk)
    kv_finish<<<dim3(MMEM + 64, BATCH), 128>>>(m_k, m_v);

    // attention over compacted keys
    attn_kernel<<<dim3(NSEQ / 128, NHEAD, BATCH), 256, ATTN_SMEM_BYTES>>>();

    // output projection
    GemmJob jo = { pa, wo, bo, pp };
    gemm_bf16<<<dim3(DMODEL / BN, Mrows / BM, 1), 256, GEMM_SMEM_BYTES>>>(jo, jo);

    ln_kernel<<<Mrows / 8, 256>>>(queries, gamma, beta, out);
}

// round 12
// speedup vs baseline: 1.5948x; 1.0181x over previous
#include <cuda_runtime.h>
#include <cuda_bf16.h>
#include <mma.h>
#include <cstdint>

using namespace nvcuda;

// ---------------------------------------------------------------------------
// Problem constants
// ---------------------------------------------------------------------------
#define BATCH 4
#define NSEQ  1024
#define DMODEL 1024
#define NHEAD 16
#define DK 64
#define MMEM 64
#define NKM (NSEQ + MMEM)   // 1088
#define EPS 1e-5f

typedef __nv_bfloat16  bf16;
typedef __nv_bfloat162 bf162;

// ---------------------------------------------------------------------------
// Scratch
// ---------------------------------------------------------------------------
__device__ bf16  g_xq [BATCH * NSEQ * DMODEL];
__device__ bf16  g_xkc[BATCH * NKM  * DMODEL];    // compacted bf16 input keys
__device__ bf16  g_xvc[BATCH * NKM  * DMODEL];    // compacted bf16 input values
__device__ bf16  g_wq[DMODEL * DMODEL];
__device__ bf16  g_wk[DMODEL * DMODEL];
__device__ bf16  g_wv[DMODEL * DMODEL];
__device__ bf16  g_wo[DMODEL * DMODEL];
__device__ bf16  g_q   [BATCH * NSEQ * DMODEL];
__device__ bf16  g_kc  [BATCH * NKM  * DMODEL];   // projected compacted K (+mem,+pad)
__device__ bf16  g_vc  [BATCH * NKM  * DMODEL];
__device__ bf16  g_attn[BATCH * NSEQ * DMODEL];
__device__ bf16  g_proj[BATCH * NSEQ * DMODEL];
__device__ int   g_pos [BATCH * NSEQ];            // compaction target (-1 = masked)
__device__ int   g_nk  [BATCH];                   // survivors per batch

// ---------------------------------------------------------------------------
// helpers
// ---------------------------------------------------------------------------
__device__ __forceinline__ uint32_t smem_u32(const void* p) {
    return (uint32_t)__cvta_generic_to_shared(p);
}
__device__ __forceinline__ void cp16(uint32_t dst, const void* src) {
    asm volatile("cp.async.cg.shared.global [%0], [%1], 16;" :: "r"(dst), "l"(src));
}
__device__ __forceinline__ void cp_commit() {
    asm volatile("cp.async.commit_group;");
}
template<int N> __device__ __forceinline__ void cp_wait() {
    asm volatile("cp.async.wait_group %0;" :: "n"(N));
}
__device__ __forceinline__ uint32_t lds_u32(uint32_t a) {
    uint32_t v;
    asm volatile("ld.shared.b32 %0, [%1];" : "=r"(v) : "r"(a));
    return v;
}
__device__ __forceinline__ void ldsm_x4(uint32_t& d0, uint32_t& d1,
                                        uint32_t& d2, uint32_t& d3, uint32_t a) {
    asm volatile("ldmatrix.sync.aligned.m8n8.x4.shared.b16 {%0,%1,%2,%3}, [%4];"
                 : "=r"(d0), "=r"(d1), "=r"(d2), "=r"(d3) : "r"(a));
}
__device__ __forceinline__ void ldsm_x4_trans(uint32_t& d0, uint32_t& d1,
                                              uint32_t& d2, uint32_t& d3, uint32_t a) {
    asm volatile("ldmatrix.sync.aligned.m8n8.x4.trans.shared.b16 {%0,%1,%2,%3}, [%4];"
                 : "=r"(d0), "=r"(d1), "=r"(d2), "=r"(d3) : "r"(a));
}
__device__ __forceinline__ void mma16816(float& c0, float& c1, float& c2, float& c3,
                                         uint32_t a0, uint32_t a1, uint32_t a2, uint32_t a3,
                                         uint32_t b0, uint32_t b1) {
    asm volatile("mma.sync.aligned.m16n8k16.row.col.f32.bf16.bf16.f32 "
                 "{%0,%1,%2,%3}, {%4,%5,%6,%7}, {%8,%9}, {%0,%1,%2,%3};"
                 : "+f"(c0), "+f"(c1), "+f"(c2), "+f"(c3)
                 : "r"(a0), "r"(a1), "r"(a2), "r"(a3), "r"(b0), "r"(b1));
}
__device__ __forceinline__ uint32_t pack_bf16x2(float lo, float hi) {
    bf162 t = __floats2bfloat162_rn(lo, hi);
    return *(uint32_t*)&t;
}

// ---------------------------------------------------------------------------
// fp32 -> bf16 conversion, 5 tensors in one launch (grid.y = job).
// ---------------------------------------------------------------------------
struct CvtJob { const float* in; bf16* out; int n; };

__global__ __launch_bounds__(256) void cvt_all(
    CvtJob j0, CvtJob j1, CvtJob j2, CvtJob j3, CvtJob j4)
{
    CvtJob j;
    switch (blockIdx.y) {
        case 0: j = j0; break; case 1: j = j1; break; case 2: j = j2; break;
        case 3: j = j3; break; default: j = j4; break;
    }
    int i = (blockIdx.x * 256 + threadIdx.x) * 8;
    if (i >= j.n) return;
    float4 v0 = *(const float4*)(j.in + i);
    float4 v1 = *(const float4*)(j.in + i + 4);
    uint4 o;
    o.x = pack_bf16x2(v0.x, v0.y); o.y = pack_bf16x2(v0.z, v0.w);
    o.z = pack_bf16x2(v1.x, v1.y); o.w = pack_bf16x2(v1.z, v1.w);
    *(uint4*)(j.out + i) = o;
}

// ---------------------------------------------------------------------------
// Mask scan: per batch, exclusive prefix positions of unmasked columns.
// ---------------------------------------------------------------------------
__global__ __launch_bounds__(1024) void mask_scan(const int* __restrict__ amask)
{
    const int b = blockIdx.x;
    const int i = threadIdx.x;
    const int lane = i & 31, w = i >> 5;
    int keep = (amask[b * NSEQ + i] == 0) ? 1 : 0;
    unsigned bal = __ballot_sync(0xffffffffu, keep);
    int before = __popc(bal & ((1u << lane) - 1));
    __shared__ int wsum[32];
    if (lane == 0) wsum[w] = __popc(bal);
    __syncthreads();
    if (w == 0) {
        int v = wsum[lane];
#pragma unroll
        for (int o = 1; o < 32; o <<= 1) {
            int t = __shfl_up_sync(0xffffffffu, v, o);
            if (lane >= o) v += t;
        }
        wsum[lane] = v;
    }
    __syncthreads();
    int base = (w == 0) ? 0 : wsum[w - 1];
    g_pos[b * NSEQ + i] = keep ? (base + before) : -1;
    if (i == 1023) g_nk[b] = wsum[31];
}

// ---------------------------------------------------------------------------
// Compact INPUT keys/values AND finish compacted K/V tail:
//   x <  NSEQ          : gather surviving fp32 rows -> bf16 at compacted pos
//   x in [NSEQ,+MMEM)  : memory rows (x8) directly into g_kc/g_vc at nk+m
//   x in [+MMEM,+64)   : zero pad rows up to KB*64
// (projection GEMM stores are predicated to rows < nk, so these survive)
// ---------------------------------------------------------------------------
__global__ __launch_bounds__(128) void compact_in(
    const float* __restrict__ keys, const float* __restrict__ values,
    const float* __restrict__ m_k, const float* __restrict__ m_v)
{
    const int b = blockIdx.y;
    const int x = blockIdx.x;
    const int t = threadIdx.x;

    if (x < NSEQ) {
        int pos = g_pos[b * NSEQ + x];
        if (pos < 0) return;
        const float4* ks = (const float4*)(keys   + ((size_t)(b * NSEQ + x)) * DMODEL);
        const float4* vs = (const float4*)(values + ((size_t)(b * NSEQ + x)) * DMODEL);
        float4 k0 = ks[t * 2], k1 = ks[t * 2 + 1];
        float4 v0 = vs[t * 2], v1 = vs[t * 2 + 1];
        uint4 ko, vo;
        ko.x = pack_bf16x2(k0.x, k0.y); ko.y = pack_bf16x2(k0.z, k0.w);
        ko.z = pack_bf16x2(k1.x, k1.y); ko.w = pack_bf16x2(k1.z, k1.w);
        vo.x = pack_bf16x2(v0.x, v0.y); vo.y = pack_bf16x2(v0.z, v0.w);
        vo.z = pack_bf16x2(v1.x, v1.y); vo.w = pack_bf16x2(v1.z, v1.w);
        ((uint4*)(g_xkc + ((size_t)(b * NKM + pos)) * DMODEL))[t] = ko;
        ((uint4*)(g_xvc + ((size_t)(b * NKM + pos)) * DMODEL))[t] = vo;
    } else if (x < NSEQ + MMEM) {
        const int nk = g_nk[b];
        int m = x - NSEQ;
        int dst = nk + m;
        const float4* mk = (const float4*)(m_k + (size_t)m * DMODEL);
        const float4* mv = (const float4*)(m_v + (size_t)m * DMODEL);
        float4 a0 = mk[t * 2], a1 = mk[t * 2 + 1];
        float4 b0 = mv[t * 2], b1 = mv[t * 2 + 1];
        uint4 ko, vo;
        ko.x = pack_bf16x2(a0.x * 8.f, a0.y * 8.f); ko.y = pack_bf16x2(a0.z * 8.f, a0.w * 8.f);
        ko.z = pack_bf16x2(a1.x * 8.f, a1.y * 8.f); ko.w = pack_bf16x2(a1.z * 8.f, a1.w * 8.f);
        vo.x = pack_bf16x2(b0.x * 8.f, b0.y * 8.f); vo.y = pack_bf16x2(b0.z * 8.f, b0.w * 8.f);
        vo.z = pack_bf16x2(b1.x * 8.f, b1.y * 8.f); vo.w = pack_bf16x2(b1.z * 8.f, b1.w * 8.f);
        ((uint4*)(g_kc + ((size_t)(b * NKM + dst)) * DMODEL))[t] = ko;
        ((uint4*)(g_vc + ((size_t)(b * NKM + dst)) * DMODEL))[t] = vo;
    } else {
        const int nk = g_nk[b];
        int p = x - NSEQ - MMEM;
        int dst = nk + MMEM + p;
        int KB = (nk + 127) >> 6;
        if (dst >= (KB << 6)) return;
        uint4 z = {0, 0, 0, 0};
        ((uint4*)(g_kc + ((size_t)(b * NKM + dst)) * DMODEL))[t] = z;
        ((uint4*)(g_vc + ((size_t)(b * NKM + dst)) * DMODEL))[t] = z;
    }
}

// ---------------------------------------------------------------------------
// BF16 GEMM tile body. C = A @ W^T + bias, 128x128 tile, BK=64, 3-stage
// cp.async, 8 warps (32x64 each). Stores predicated to rows < vrows.
// ---------------------------------------------------------------------------
#define BM 128
#define BN 128
#define BKD 64
#define PKH 72
#define STAGEH (BM * PKH)                        // 9216 halves
#define GEMM_SMEM_BYTES (6 * STAGEH * 2)         // 110592 B
#define EPI_LD 132

__device__ __forceinline__ void gemm_tile(
    const bf16* __restrict__ A, const bf16* __restrict__ W,
    const float* __restrict__ bias, bf16* __restrict__ C,
    size_t arow0, int col0, int vrows, bf16* smh)
{
    bf16* Abuf[3] = { smh, smh + 2 * STAGEH, smh + 4 * STAGEH };
    bf16* Bbuf[3] = { smh + STAGEH, smh + 3 * STAGEH, smh + 5 * STAGEH };

    const int tid  = threadIdx.x;
    const int warp = tid >> 5;
    const int wr   = warp & 3;
    const int wc   = warp >> 2;
    const int K = DMODEL;
    const int NIT = K / BKD;   // 16
    const int lr = tid >> 3, lc = tid & 7;

    wmma::fragment<wmma::accumulator, 16, 16, 16, float> acc[2][4];
#pragma unroll
    for (int i = 0; i < 2; i++)
#pragma unroll
        for (int c = 0; c < 4; c++) wmma::fill_fragment(acc[i][c], 0.0f);

#pragma unroll
    for (int s = 0; s < 2; s++) {
        int kb = s * BKD;
#pragma unroll
        for (int t = 0; t < 4; t++) {
            int r = lr + t * 32;
            cp16(smem_u32(&Abuf[s][r * PKH + lc * 8]), &A[(arow0 + r) * K + kb + lc * 8]);
            cp16(smem_u32(&Bbuf[s][r * PKH + lc * 8]), &W[(size_t)(col0 + r) * K + kb + lc * 8]);
        }
        cp_commit();
    }

    for (int it = 0; it < NIT; ++it) {
        if (it + 1 < NIT) cp_wait<1>(); else cp_wait<0>();
        __syncthreads();

        if (it + 2 < NIT) {
            int kb = (it + 2) * BKD;
            int st = (it + 2) % 3;
#pragma unroll
            for (int t = 0; t < 4; t++) {
                int r = lr + t * 32;
                cp16(smem_u32(&Abuf[st][r * PKH + lc * 8]), &A[(arow0 + r) * K + kb + lc * 8]);
                cp16(smem_u32(&Bbuf[st][r * PKH + lc * 8]), &W[(size_t)(col0 + r) * K + kb + lc * 8]);
            }
            cp_commit();
        }

        const bf16* Ap = Abuf[it % 3];
        const bf16* Bp = Bbuf[it % 3];
#pragma unroll
        for (int ks = 0; ks < BKD / 16; ks++) {
            wmma::fragment<wmma::matrix_a, 16, 16, 16, bf16, wmma::row_major> a0, a1;
            wmma::fragment<wmma::matrix_b, 16, 16, 16, bf16, wmma::col_major> b[4];
            wmma::load_matrix_sync(a0, &Ap[(wr * 32     ) * PKH + ks * 16], PKH);
            wmma::load_matrix_sync(a1, &Ap[(wr * 32 + 16) * PKH + ks * 16], PKH);
#pragma unroll
            for (int c = 0; c < 4; c++)
                wmma::load_matrix_sync(b[c], &Bp[(wc * 64 + c * 16) * PKH + ks * 16], PKH);
#pragma unroll
            for (int c = 0; c < 4; c++) {
                wmma::mma_sync(acc[0][c], a0, b[c], acc[0][c]);
                wmma::mma_sync(acc[1][c], a1, b[c], acc[1][c]);
            }
        }
    }
    __syncthreads();

    float (*Cs)[EPI_LD] = (float (*)[EPI_LD])smh;
#pragma unroll
    for (int i = 0; i < 2; i++)
#pragma unroll
        for (int c = 0; c < 4; c++)
            wmma::store_matrix_sync(&Cs[wr * 32 + i * 16][wc * 64 + c * 16],
                                    acc[i][c], EPI_LD, wmma::mem_row_major);
    __syncthreads();

#pragma unroll
    for (int t = 0; t < 8; t++) {
        int ch = tid + t * 256;
        int r = ch >> 4, c8 = ch & 15;
        if (r >= vrows) continue;
        const float* src = &Cs[r][c8 * 8];
        const float* bp  = &bias[col0 + c8 * 8];
        uint4 o;
        o.x = pack_bf16x2(src[0] + bp[0], src[1] + bp[1]);
        o.y = pack_bf16x2(src[2] + bp[2], src[3] + bp[3]);
        o.z = pack_bf16x2(src[4] + bp[4], src[5] + bp[5]);
        o.w = pack_bf16x2(src[6] + bp[6], src[7] + bp[7]);
        *(uint4*)&C[(arow0 + r) * DMODEL + col0 + c8 * 8] = o;
    }
}

// Merged Q/K/V projection launch. z=0: Q dense. z=1/2: K/V compacted with
// early exit past the padded survivor count and stores predicated to < nk.
__global__ __launch_bounds__(256, 2) void proj_gemm(
    const float* bq, const float* bk, const float* bv)
{
    extern __shared__ bf16 smh[];
    const int z = blockIdx.z;
    if (z == 0) {
        gemm_tile(g_xq, g_wq, bq, g_q,
                  (size_t)blockIdx.y * BM, blockIdx.x * BN, BM, smh);
    } else {
        const int b  = blockIdx.y >> 3;
        const int rt = blockIdx.y & 7;
        const int nk = g_nk[b];
        const int nkpad = (nk + 127) & ~127;
        if (rt * BM >= nkpad) return;
        const int vrows = min(BM, nk - rt * BM);
        if (z == 1)
            gemm_tile(g_xkc, g_wk, bk, g_kc,
                      (size_t)b * NKM + rt * BM, blockIdx.x * BN, vrows, smh);
        else
            gemm_tile(g_xvc, g_wv, bv, g_vc,
                      (size_t)b * NKM + rt * BM, blockIdx.x * BN, vrows, smh);
    }
}

// Dense GEMM launch (Wo projection).
struct GemmJob { const bf16* A; const bf16* W; const float* bias; bf16* C; };

__global__ __launch_bounds__(256, 2) void gemm_bf16(GemmJob j)
{
    extern __shared__ bf16 smh[];
    gemm_tile(j.A, j.W, j.bias, j.C,
              (size_t)blockIdx.y * BM, blockIdx.x * BN, BM, smh);
}

// ---------------------------------------------------------------------------
// Attention on COMPACTED K/V. No masking; pad columns (zero K) contribute
// exp(0)=1 to the sum, corrected exactly by subtracting npad.
// ---------------------------------------------------------------------------
#define LDQ 72
#define LDKV 72
#define ATTN_SMEM_BYTES ((128 * LDQ + 4 * 64 * LDKV) * 2)  // 55296

__global__ __launch_bounds__(256, 2) void attn_kernel()
{
    extern __shared__ char smraw[];
    bf16* Qs  = (bf16*)smraw;
    bf16* Kb0 = Qs + 128 * LDQ;
    bf16* Kb1 = Kb0 + 64 * LDKV;
    bf16* Vb0 = Kb1 + 64 * LDKV;
    bf16* Vb1 = Vb0 + 64 * LDKV;

    const int qt = blockIdx.x, h = blockIdx.y, b = blockIdx.z;
    const int tid  = threadIdx.x;
    const int warp = tid >> 5;
    const int lane = tid & 31;
    const int r = lane >> 2;
    const int c = lane & 3;
    const int lr = tid >> 3, lc8 = tid & 7;
    const int lrow8 = lane & 7;
    const int ksel  = (lane >> 3) & 1;
    const int nsel  = (lane >> 4) & 1;
    const int g  = lane >> 3;
    const int rw = lane & 7;

    const int nk = g_nk[b];
    const int KB = (nk + 127) >> 6;
    const float fpad = (float)((KB << 6) - nk - MMEM);

    const bf16* qbase = g_q + ((size_t)(b * NSEQ + qt * 128)) * DMODEL + h * DK;
    const bf16* kroot = g_kc + ((size_t)(b * NKM)) * DMODEL + h * DK;
    const bf16* vroot = g_vc + ((size_t)(b * NKM)) * DMODEL + h * DK;

#pragma unroll
    for (int t = 0; t < 4; t++) {
        int row = lr + t * 32;
        cp16(smem_u32(&Qs[row * LDQ + lc8 * 8]), &qbase[(size_t)row * DMODEL + lc8 * 8]);
    }
    cp_commit();

#pragma unroll
    for (int t = 0; t < 2; t++) {
        int row = lr + t * 32;
        cp16(smem_u32(&Kb0[row * LDKV + lc8 * 8]), &kroot[(size_t)row * DMODEL + lc8 * 8]);
        cp16(smem_u32(&Vb0[row * LDKV + lc8 * 8]), &vroot[(size_t)row * DMODEL + lc8 * 8]);
    }
    cp_commit();

    cp_wait<1>();
    __syncthreads();

    uint32_t qf[4][4];
    {
        uint32_t q0 = smem_u32(&Qs[(warp * 16 + r) * LDQ]) + 4 * c;
        uint32_t q8 = q0 + 8 * LDQ * 2;
#pragma unroll
        for (int kc = 0; kc < 4; kc++) {
            qf[kc][0] = lds_u32(q0 + kc * 32);
            qf[kc][1] = lds_u32(q8 + kc * 32);
            qf[kc][2] = lds_u32(q0 + kc * 32 + 16);
            qf[kc][3] = lds_u32(q8 + kc * 32 + 16);
        }
    }

    float oacc[8][4];
#pragma unroll
    for (int ot = 0; ot < 8; ot++)
#pragma unroll
        for (int i = 0; i < 4; i++) oacc[ot][i] = 0.0f;
    float sum0 = 0.0f, sum1 = 0.0f;

    for (int kb = 0; kb < KB; kb++) {
        const bf16* Kp = (kb & 1) ? Kb1 : Kb0;
        const bf16* Vp = (kb & 1) ? Vb1 : Vb0;

        cp_wait<0>();
        __syncthreads();

        if (kb + 1 < KB) {
            bf16* Kn = (kb & 1) ? Kb0 : Kb1;
            bf16* Vn = (kb & 1) ? Vb0 : Vb1;
            const bf16* kp = kroot + (size_t)(kb + 1) * 64 * DMODEL;
            const bf16* vp = vroot + (size_t)(kb + 1) * 64 * DMODEL;
#pragma unroll
            for (int t = 0; t < 2; t++) {
                int row = lr + t * 32;
                cp16(smem_u32(&Kn[row * LDKV + lc8 * 8]), &kp[(size_t)row * DMODEL + lc8 * 8]);
                cp16(smem_u32(&Vn[row * LDKV + lc8 * 8]), &vp[(size_t)row * DMODEL + lc8 * 8]);
            }
            cp_commit();
        }

        float sc[8][4];
#pragma unroll
        for (int nt = 0; nt < 8; nt++)
#pragma unroll
            for (int i = 0; i < 4; i++) sc[nt][i] = 0.0f;

        const uint32_t kfb = smem_u32(Kp) + ((nsel * 8 + lrow8) * LDKV + ksel * 8) * 2;
#pragma unroll
        for (int kc = 0; kc < 4; kc++) {
#pragma unroll
            for (int ng = 0; ng < 4; ng++) {
                uint32_t b0, b1, b2, b3;
                ldsm_x4(b0, b1, b2, b3, kfb + (ng * 16 * LDKV + kc * 16) * 2);
                mma16816(sc[2 * ng][0], sc[2 * ng][1], sc[2 * ng][2], sc[2 * ng][3],
                         qf[kc][0], qf[kc][1], qf[kc][2], qf[kc][3], b0, b1);
                mma16816(sc[2 * ng + 1][0], sc[2 * ng + 1][1], sc[2 * ng + 1][2], sc[2 * ng + 1][3],
                         qf[kc][0], qf[kc][1], qf[kc][2], qf[kc][3], b2, b3);
            }
        }

        uint32_t pf[8][2];
#pragma unroll
        for (int nt = 0; nt < 8; nt++) {
            float p00 = __expf(sc[nt][0] * 0.125f);
            float p01 = __expf(sc[nt][1] * 0.125f);
            float p10 = __expf(sc[nt][2] * 0.125f);
            float p11 = __expf(sc[nt][3] * 0.125f);
            sum0 += p00 + p01;
            sum1 += p10 + p11;
            pf[nt][0] = pack_bf16x2(p00, p01);
            pf[nt][1] = pack_bf16x2(p10, p11);
        }

        const uint32_t vbase = smem_u32(Vp);
#pragma unroll
        for (int kc = 0; kc < 4; kc++) {
            uint32_t a0 = pf[2 * kc][0], a1 = pf[2 * kc][1];
            uint32_t a2 = pf[2 * kc + 1][0], a3 = pf[2 * kc + 1][1];
#pragma unroll
            for (int op = 0; op < 4; op++) {
                uint32_t addr = vbase +
                    ((16 * kc + (g & 1) * 8 + rw) * LDKV + (op * 2 + (g >> 1)) * 8) * 2;
                uint32_t b0, b1, b2, b3;
                ldsm_x4_trans(b0, b1, b2, b3, addr);
                mma16816(oacc[op * 2][0], oacc[op * 2][1], oacc[op * 2][2], oacc[op * 2][3],
                         a0, a1, a2, a3, b0, b1);
                mma16816(oacc[op * 2 + 1][0], oacc[op * 2 + 1][1],
                         oacc[op * 2 + 1][2], oacc[op * 2 + 1][3],
                         a0, a1, a2, a3, b2, b3);
            }
        }
    }

    sum0 += __shfl_xor_sync(0xffffffffu, sum0, 1);
    sum0 += __shfl_xor_sync(0xffffffffu, sum0, 2);
    sum1 += __shfl_xor_sync(0xffffffffu, sum1, 1);
    sum1 += __shfl_xor_sync(0xffffffffu, sum1, 2);
    const float inv0 = 1.0f / (sum0 - fpad);
    const float inv1 = 1.0f / (sum1 - fpad);

    bf16* ob = g_attn + ((size_t)(b * NSEQ + qt * 128 + warp * 16 + r)) * DMODEL + h * DK + 2 * c;
#pragma unroll
    for (int ot = 0; ot < 8; ot++) {
        *(uint32_t*)&ob[ot * 8] =
            pack_bf16x2(oacc[ot][0] * inv0, oacc[ot][1] * inv0);
        *(uint32_t*)&ob[8 * DMODEL + ot * 8] =
            pack_bf16x2(oacc[ot][2] * inv1, oacc[ot][3] * inv1);
    }
}

// ---------------------------------------------------------------------------
// Residual + LayerNorm. One warp per row. proj is bf16.
// ---------------------------------------------------------------------------
__global__ __launch_bounds__(256) void ln_kernel(
    const float* __restrict__ queries, const float* __restrict__ gamma,
    const float* __restrict__ beta, float* __restrict__ out)
{
    const int row  = blockIdx.x * 8 + (threadIdx.x >> 5);
    const int lane = threadIdx.x & 31;
    const float4* xin = (const float4*)(queries + (size_t)row * DMODEL);
    const uint4*  pin = (const uint4*)(g_proj + (size_t)row * DMODEL);

    float x[32];
    float s = 0.0f;
#pragma unroll
    for (int i = 0; i < 4; i++) {
        int ch = lane + i * 32;
        float4 a0 = xin[ch * 2];
        float4 a1 = xin[ch * 2 + 1];
        uint4 p = pin[ch];
        const bf162* ph = (const bf162*)&p;
        float2 p0 = __bfloat1622float2(ph[0]);
        float2 p1 = __bfloat1622float2(ph[1]);
        float2 p2 = __bfloat1622float2(ph[2]);
        float2 p3 = __bfloat1622float2(ph[3]);
        x[i * 8 + 0] = a0.x + p0.x; x[i * 8 + 1] = a0.y + p0.y;
        x[i * 8 + 2] = a0.z + p1.x; x[i * 8 + 3] = a0.w + p1.y;
        x[i * 8 + 4] = a1.x + p2.x; x[i * 8 + 5] = a1.y + p2.y;
        x[i * 8 + 6] = a1.z + p3.x; x[i * 8 + 7] = a1.w + p3.y;
#pragma unroll
        for (int k = 0; k < 8; k++) s += x[i * 8 + k];
    }
#pragma unroll
    for (int o = 16; o; o >>= 1) s += __shfl_xor_sync(0xffffffffu, s, o);
    const float mu = s * (1.0f / DMODEL);

    float v = 0.0f;
#pragma unroll
    for (int i = 0; i < 32; i++) { float d = x[i] - mu; v += d * d; }
#pragma unroll
    for (int o = 16; o; o >>= 1) v += __shfl_xor_sync(0xffffffffu, v, o);
    const float rs = rsqrtf(v * (1.0f / DMODEL) + EPS);

    float4* op = (float4*)(out + (size_t)row * DMODEL);
    const float4* gp = (const float4*)gamma;
    const float4* bp = (const float4*)beta;
#pragma unroll
    for (int i = 0; i < 4; i++) {
        int ch = lane + i * 32;
#pragma unroll
        for (int half = 0; half < 2; half++) {
            float4 g  = gp[ch * 2 + half];
            float4 be = bp[ch * 2 + half];
            float4 o4;
            o4.x = (x[i * 8 + half * 4 + 0] - mu) * rs * g.x + be.x;
            o4.y = (x[i * 8 + half * 4 + 1] - mu) * rs * g.y + be.y;
            o4.z = (x[i * 8 + half * 4 + 2] - mu) * rs * g.z + be.z;
            o4.w = (x[i * 8 + half * 4 + 3] - mu) * rs * g.w + be.w;
            op[ch * 2 + half] = o4;
        }
    }
}

// ---------------------------------------------------------------------------
// Launch
// ---------------------------------------------------------------------------
extern "C" void kernel_launch(void* const* d_in, const int* in_sizes, int n_in,
                              void* d_out, int out_size)
{
    const float* queries = (const float*)d_in[0];
    const float* keys    = (const float*)d_in[1];
    const float* values  = (const float*)d_in[2];
    const int*   amask   = (const int*)  d_in[3];
    const float* Wq = (const float*)d_in[4],  *bq = (const float*)d_in[5];
    const float* Wk = (const float*)d_in[6],  *bk = (const float*)d_in[7];
    const float* Wv = (const float*)d_in[8],  *bv = (const float*)d_in[9];
    const float* Wo = (const float*)d_in[10], *bo = (const float*)d_in[11];
    const float* m_k = (const float*)d_in[12], *m_v = (const float*)d_in[13];
    const float* gamma = (const float*)d_in[14], *beta = (const float*)d_in[15];
    float* out = (float*)d_out;

    bf16 *xq, *wq, *wk, *wv, *wo, *pa, *pp;
    cudaGetSymbolAddress((void**)&xq, g_xq);
    cudaGetSymbolAddress((void**)&wq, g_wq);
    cudaGetSymbolAddress((void**)&wk, g_wk);
    cudaGetSymbolAddress((void**)&wv, g_wv);
    cudaGetSymbolAddress((void**)&wo, g_wo);
    cudaGetSymbolAddress((void**)&pa, g_attn);
    cudaGetSymbolAddress((void**)&pp, g_proj);

    cudaFuncSetAttribute(proj_gemm,
                         cudaFuncAttributeMaxDynamicSharedMemorySize, GEMM_SMEM_BYTES);
    cudaFuncSetAttribute(gemm_bf16,
                         cudaFuncAttributeMaxDynamicSharedMemorySize, GEMM_SMEM_BYTES);
    cudaFuncSetAttribute(attn_kernel,
                         cudaFuncAttributeMaxDynamicSharedMemorySize, ATTN_SMEM_BYTES);

    const int Mrows = BATCH * NSEQ;        // 4096
    const int NACT  = Mrows * DMODEL;      // 4M
    const int NWEI  = DMODEL * DMODEL;     // 1M

    CvtJob cj0 = { queries, xq, NACT };
    CvtJob cj1 = { Wq, wq, NWEI };
    CvtJob cj2 = { Wk, wk, NWEI };
    CvtJob cj3 = { Wv, wv, NWEI };
    CvtJob cj4 = { Wo, wo, NWEI };
    cvt_all<<<dim3(NACT / 2048, 5), 256>>>(cj0, cj1, cj2, cj3, cj4);

    mask_scan<<<BATCH, 1024>>>(amask);

    // compact inputs + memory rows + zero pad (one launch)
    compact_in<<<dim3(NSEQ + MMEM + 64, BATCH), 128>>>(keys, values, m_k, m_v);

    // merged Q/K/V projections (Q dense; K/V compacted, predicated stores)
    proj_gemm<<<dim3(DMODEL / BN, Mrows / BM, 3), 256, GEMM_SMEM_BYTES>>>(bq, bk, bv);

    // attention over compacted keys
    attn_kernel<<<dim3(NSEQ / 128, NHEAD, BATCH), 256, ATTN_SMEM_BYTES>>>();

    // output projection
    GemmJob jo = { pa, wo, bo, pp };
    gemm_bf16<<<dim3(DMODEL / BN, Mrows / BM, 1), 256, GEMM_SMEM_BYTES>>>(jo);

    ln_kernel<<<Mrows / 8, 256>>>(queries, gamma, beta, out);
}

// round 13
// speedup vs baseline: 1.5983x; 1.0022x over previous
#include <cuda_runtime.h>
#include <cuda_bf16.h>
#include <mma.h>
#include <cstdint>

using namespace nvcuda;

// ---------------------------------------------------------------------------
// Problem constants
// ---------------------------------------------------------------------------
#define BATCH 4
#define NSEQ  1024
#define DMODEL 1024
#define NHEAD 16
#define DK 64
#define MMEM 64
#define NKM (NSEQ + MMEM)   // 1088
#define EPS 1e-5f

typedef __nv_bfloat16  bf16;
typedef __nv_bfloat162 bf162;

// ---------------------------------------------------------------------------
// Scratch
// ---------------------------------------------------------------------------
__device__ bf16  g_xq [BATCH * NSEQ * DMODEL];
__device__ bf16  g_xkc[BATCH * NKM  * DMODEL];    // compacted bf16 input keys
__device__ bf16  g_xvc[BATCH * NKM  * DMODEL];    // compacted bf16 input values
__device__ bf16  g_wq[DMODEL * DMODEL];
__device__ bf16  g_wk[DMODEL * DMODEL];
__device__ bf16  g_wv[DMODEL * DMODEL];
__device__ bf16  g_wo[DMODEL * DMODEL];
__device__ bf16  g_q   [BATCH * NSEQ * DMODEL];
__device__ bf16  g_kc  [BATCH * NKM  * DMODEL];   // projected compacted K (+mem,+pad)
__device__ bf16  g_vc  [BATCH * NKM  * DMODEL];
__device__ bf16  g_attn[BATCH * NSEQ * DMODEL];
__device__ bf16  g_proj[BATCH * NSEQ * DMODEL];
__device__ int   g_pos [BATCH * NSEQ];            // compaction target (-1 = masked)
__device__ int   g_nk  [BATCH];                   // survivors per batch

// ---------------------------------------------------------------------------
// helpers
// ---------------------------------------------------------------------------
__device__ __forceinline__ uint32_t smem_u32(const void* p) {
    return (uint32_t)__cvta_generic_to_shared(p);
}
__device__ __forceinline__ void cp16(uint32_t dst, const void* src) {
    asm volatile("cp.async.cg.shared.global [%0], [%1], 16;" :: "r"(dst), "l"(src));
}
__device__ __forceinline__ void cp_commit() {
    asm volatile("cp.async.commit_group;");
}
template<int N> __device__ __forceinline__ void cp_wait() {
    asm volatile("cp.async.wait_group %0;" :: "n"(N));
}
__device__ __forceinline__ uint32_t lds_u32(uint32_t a) {
    uint32_t v;
    asm volatile("ld.shared.b32 %0, [%1];" : "=r"(v) : "r"(a));
    return v;
}
__device__ __forceinline__ void ldsm_x4(uint32_t& d0, uint32_t& d1,
                                        uint32_t& d2, uint32_t& d3, uint32_t a) {
    asm volatile("ldmatrix.sync.aligned.m8n8.x4.shared.b16 {%0,%1,%2,%3}, [%4];"
                 : "=r"(d0), "=r"(d1), "=r"(d2), "=r"(d3) : "r"(a));
}
__device__ __forceinline__ void ldsm_x4_trans(uint32_t& d0, uint32_t& d1,
                                              uint32_t& d2, uint32_t& d3, uint32_t a) {
    asm volatile("ldmatrix.sync.aligned.m8n8.x4.trans.shared.b16 {%0,%1,%2,%3}, [%4];"
                 : "=r"(d0), "=r"(d1), "=r"(d2), "=r"(d3) : "r"(a));
}
__device__ __forceinline__ void mma16816(float& c0, float& c1, float& c2, float& c3,
                                         uint32_t a0, uint32_t a1, uint32_t a2, uint32_t a3,
                                         uint32_t b0, uint32_t b1) {
    asm volatile("mma.sync.aligned.m16n8k16.row.col.f32.bf16.bf16.f32 "
                 "{%0,%1,%2,%3}, {%4,%5,%6,%7}, {%8,%9}, {%0,%1,%2,%3};"
                 : "+f"(c0), "+f"(c1), "+f"(c2), "+f"(c3)
                 : "r"(a0), "r"(a1), "r"(a2), "r"(a3), "r"(b0), "r"(b1));
}
__device__ __forceinline__ uint32_t pack_bf16x2(float lo, float hi) {
    bf162 t = __floats2bfloat162_rn(lo, hi);
    return *(uint32_t*)&t;
}

// ---------------------------------------------------------------------------
// fp32 -> bf16 conversion (5 tensors) + mask scan, one launch (grid.y = job).
// Job 5 = mask scan: blocks 0..BATCH-1 only, 256 threads x 4 mask entries.
// ---------------------------------------------------------------------------
struct CvtJob { const float* in; bf16* out; int n; };

__global__ __launch_bounds__(256) void cvt_all(
    CvtJob j0, CvtJob j1, CvtJob j2, CvtJob j3, CvtJob j4,
    const int* __restrict__ amask)
{
    if (blockIdx.y == 5) {
        // ---- mask scan ----
        const int b = blockIdx.x;
        if (b >= BATCH) return;
        const int tid = threadIdx.x;
        const int lane = tid & 31, w = tid >> 5;
        int k[4], cnt = 0;
#pragma unroll
        for (int j = 0; j < 4; j++) {
            k[j] = (amask[b * NSEQ + tid * 4 + j] == 0) ? 1 : 0;
            cnt += k[j];
        }
        // inclusive warp scan of per-thread counts
        int incl = cnt;
#pragma unroll
        for (int o = 1; o < 32; o <<= 1) {
            int t = __shfl_up_sync(0xffffffffu, incl, o);
            if (lane >= o) incl += t;
        }
        __shared__ int wsum[8];
        if (lane == 31) wsum[w] = incl;
        __syncthreads();
        if (w == 0 && lane < 8) {
            int v = wsum[lane];
#pragma unroll
            for (int o = 1; o < 8; o <<= 1) {
                int t = __shfl_up_sync(0xffu, v, o);
                if (lane >= o) v += t;
            }
            wsum[lane] = v;   // inclusive scan of warp totals
        }
        __syncthreads();
        int base = ((w == 0) ? 0 : wsum[w - 1]) + incl - cnt;  // exclusive prefix
#pragma unroll
        for (int j = 0; j < 4; j++) {
            g_pos[b * NSEQ + tid * 4 + j] = k[j] ? base : -1;
            base += k[j];
        }
        if (tid == 255) g_nk[b] = wsum[7];
        return;
    }

    CvtJob j;
    switch (blockIdx.y) {
        case 0: j = j0; break; case 1: j = j1; break; case 2: j = j2; break;
        case 3: j = j3; break; default: j = j4; break;
    }
    int i = (blockIdx.x * 256 + threadIdx.x) * 8;
    if (i >= j.n) return;
    float4 v0 = *(const float4*)(j.in + i);
    float4 v1 = *(const float4*)(j.in + i + 4);
    uint4 o;
    o.x = pack_bf16x2(v0.x, v0.y); o.y = pack_bf16x2(v0.z, v0.w);
    o.z = pack_bf16x2(v1.x, v1.y); o.w = pack_bf16x2(v1.z, v1.w);
    *(uint4*)(j.out + i) = o;
}

// ---------------------------------------------------------------------------
// Compact INPUT keys/values AND finish compacted K/V tail:
//   x <  NSEQ          : gather surviving fp32 rows -> bf16 at compacted pos
//   x in [NSEQ,+MMEM)  : memory rows (x8) directly into g_kc/g_vc at nk+m
//   x in [+MMEM,+64)   : zero pad rows up to KB*64
// (projection GEMM stores are predicated to rows < nk, so these survive)
// ---------------------------------------------------------------------------
__global__ __launch_bounds__(128) void compact_in(
    const float* __restrict__ keys, const float* __restrict__ values,
    const float* __restrict__ m_k, const float* __restrict__ m_v)
{
    const int b = blockIdx.y;
    const int x = blockIdx.x;
    const int t = threadIdx.x;

    if (x < NSEQ) {
        int pos = g_pos[b * NSEQ + x];
        if (pos < 0) return;
        const float4* ks = (const float4*)(keys   + ((size_t)(b * NSEQ + x)) * DMODEL);
        const float4* vs = (const float4*)(values + ((size_t)(b * NSEQ + x)) * DMODEL);
        float4 k0 = ks[t * 2], k1 = ks[t * 2 + 1];
        float4 v0 = vs[t * 2], v1 = vs[t * 2 + 1];
        uint4 ko, vo;
        ko.x = pack_bf16x2(k0.x, k0.y); ko.y = pack_bf16x2(k0.z, k0.w);
        ko.z = pack_bf16x2(k1.x, k1.y); ko.w = pack_bf16x2(k1.z, k1.w);
        vo.x = pack_bf16x2(v0.x, v0.y); vo.y = pack_bf16x2(v0.z, v0.w);
        vo.z = pack_bf16x2(v1.x, v1.y); vo.w = pack_bf16x2(v1.z, v1.w);
        ((uint4*)(g_xkc + ((size_t)(b * NKM + pos)) * DMODEL))[t] = ko;
        ((uint4*)(g_xvc + ((size_t)(b * NKM + pos)) * DMODEL))[t] = vo;
    } else if (x < NSEQ + MMEM) {
        const int nk = g_nk[b];
        int m = x - NSEQ;
        int dst = nk + m;
        const float4* mk = (const float4*)(m_k + (size_t)m * DMODEL);
        const float4* mv = (const float4*)(m_v + (size_t)m * DMODEL);
        float4 a0 = mk[t * 2], a1 = mk[t * 2 + 1];
        float4 b0 = mv[t * 2], b1 = mv[t * 2 + 1];
        uint4 ko, vo;
        ko.x = pack_bf16x2(a0.x * 8.f, a0.y * 8.f); ko.y = pack_bf16x2(a0.z * 8.f, a0.w * 8.f);
        ko.z = pack_bf16x2(a1.x * 8.f, a1.y * 8.f); ko.w = pack_bf16x2(a1.z * 8.f, a1.w * 8.f);
        vo.x = pack_bf16x2(b0.x * 8.f, b0.y * 8.f); vo.y = pack_bf16x2(b0.z * 8.f, b0.w * 8.f);
        vo.z = pack_bf16x2(b1.x * 8.f, b1.y * 8.f); vo.w = pack_bf16x2(b1.z * 8.f, b1.w * 8.f);
        ((uint4*)(g_kc + ((size_t)(b * NKM + dst)) * DMODEL))[t] = ko;
        ((uint4*)(g_vc + ((size_t)(b * NKM + dst)) * DMODEL))[t] = vo;
    } else {
        const int nk = g_nk[b];
        int p = x - NSEQ - MMEM;
        int dst = nk + MMEM + p;
        int KB = (nk + 127) >> 6;
        if (dst >= (KB << 6)) return;
        uint4 z = {0, 0, 0, 0};
        ((uint4*)(g_kc + ((size_t)(b * NKM + dst)) * DMODEL))[t] = z;
        ((uint4*)(g_vc + ((size_t)(b * NKM + dst)) * DMODEL))[t] = z;
    }
}

// ---------------------------------------------------------------------------
// BF16 GEMM tile body. C = A @ W^T + bias, 128x128 tile, BK=64, 3-stage
// cp.async, 8 warps (32x64 each). Stores predicated to rows < vrows.
// ---------------------------------------------------------------------------
#define BM 128
#define BN 128
#define BKD 64
#define PKH 72
#define STAGEH (BM * PKH)                        // 9216 halves
#define GEMM_SMEM_BYTES (6 * STAGEH * 2)         // 110592 B
#define EPI_LD 132

__device__ __forceinline__ void gemm_tile(
    const bf16* __restrict__ A, const bf16* __restrict__ W,
    const float* __restrict__ bias, bf16* __restrict__ C,
    size_t arow0, int col0, int vrows, bf16* smh)
{
    bf16* Abuf[3] = { smh, smh + 2 * STAGEH, smh + 4 * STAGEH };
    bf16* Bbuf[3] = { smh + STAGEH, smh + 3 * STAGEH, smh + 5 * STAGEH };

    const int tid  = threadIdx.x;
    const int warp = tid >> 5;
    const int wr   = warp & 3;
    const int wc   = warp >> 2;
    const int K = DMODEL;
    const int NIT = K / BKD;   // 16
    const int lr = tid >> 3, lc = tid & 7;

    wmma::fragment<wmma::accumulator, 16, 16, 16, float> acc[2][4];
#pragma unroll
    for (int i = 0; i < 2; i++)
#pragma unroll
        for (int c = 0; c < 4; c++) wmma::fill_fragment(acc[i][c], 0.0f);

#pragma unroll
    for (int s = 0; s < 2; s++) {
        int kb = s * BKD;
#pragma unroll
        for (int t = 0; t < 4; t++) {
            int r = lr + t * 32;
            cp16(smem_u32(&Abuf[s][r * PKH + lc * 8]), &A[(arow0 + r) * K + kb + lc * 8]);
            cp16(smem_u32(&Bbuf[s][r * PKH + lc * 8]), &W[(size_t)(col0 + r) * K + kb + lc * 8]);
        }
        cp_commit();
    }

    for (int it = 0; it < NIT; ++it) {
        if (it + 1 < NIT) cp_wait<1>(); else cp_wait<0>();
        __syncthreads();

        if (it + 2 < NIT) {
            int kb = (it + 2) * BKD;
            int st = (it + 2) % 3;
#pragma unroll
            for (int t = 0; t < 4; t++) {
                int r = lr + t * 32;
                cp16(smem_u32(&Abuf[st][r * PKH + lc * 8]), &A[(arow0 + r) * K + kb + lc * 8]);
                cp16(smem_u32(&Bbuf[st][r * PKH + lc * 8]), &W[(size_t)(col0 + r) * K + kb + lc * 8]);
            }
            cp_commit();
        }

        const bf16* Ap = Abuf[it % 3];
        const bf16* Bp = Bbuf[it % 3];
#pragma unroll
        for (int ks = 0; ks < BKD / 16; ks++) {
            wmma::fragment<wmma::matrix_a, 16, 16, 16, bf16, wmma::row_major> a0, a1;
            wmma::fragment<wmma::matrix_b, 16, 16, 16, bf16, wmma::col_major> b[4];
            wmma::load_matrix_sync(a0, &Ap[(wr * 32     ) * PKH + ks * 16], PKH);
            wmma::load_matrix_sync(a1, &Ap[(wr * 32 + 16) * PKH + ks * 16], PKH);
#pragma unroll
            for (int c = 0; c < 4; c++)
                wmma::load_matrix_sync(b[c], &Bp[(wc * 64 + c * 16) * PKH + ks * 16], PKH);
#pragma unroll
            for (int c = 0; c < 4; c++) {
                wmma::mma_sync(acc[0][c], a0, b[c], acc[0][c]);
                wmma::mma_sync(acc[1][c], a1, b[c], acc[1][c]);
            }
        }
    }
    __syncthreads();

    float (*Cs)[EPI_LD] = (float (*)[EPI_LD])smh;
#pragma unroll
    for (int i = 0; i < 2; i++)
#pragma unroll
        for (int c = 0; c < 4; c++)
            wmma::store_matrix_sync(&Cs[wr * 32 + i * 16][wc * 64 + c * 16],
                                    acc[i][c], EPI_LD, wmma::mem_row_major);
    __syncthreads();

#pragma unroll
    for (int t = 0; t < 8; t++) {
        int ch = tid + t * 256;
        int r = ch >> 4, c8 = ch & 15;
        if (r >= vrows) continue;
        const float* src = &Cs[r][c8 * 8];
        const float* bp  = &bias[col0 + c8 * 8];
        uint4 o;
        o.x = pack_bf16x2(src[0] + bp[0], src[1] + bp[1]);
        o.y = pack_bf16x2(src[2] + bp[2], src[3] + bp[3]);
        o.z = pack_bf16x2(src[4] + bp[4], src[5] + bp[5]);
        o.w = pack_bf16x2(src[6] + bp[6], src[7] + bp[7]);
        *(uint4*)&C[(arow0 + r) * DMODEL + col0 + c8 * 8] = o;
    }
}

// Merged Q/K/V projection launch. z=0: Q dense. z=1/2: K/V compacted with
// early exit past the padded survivor count and stores predicated to < nk.
__global__ __launch_bounds__(256, 2) void proj_gemm(
    const float* bq, const float* bk, const float* bv)
{
    extern __shared__ bf16 smh[];
    const int z = blockIdx.z;
    if (z == 0) {
        gemm_tile(g_xq, g_wq, bq, g_q,
                  (size_t)blockIdx.y * BM, blockIdx.x * BN, BM, smh);
    } else {
        const int b  = blockIdx.y >> 3;
        const int rt = blockIdx.y & 7;
        const int nk = g_nk[b];
        const int nkpad = (nk + 127) & ~127;
        if (rt * BM >= nkpad) return;
        const int vrows = min(BM, nk - rt * BM);
        if (z == 1)
            gemm_tile(g_xkc, g_wk, bk, g_kc,
                      (size_t)b * NKM + rt * BM, blockIdx.x * BN, vrows, smh);
        else
            gemm_tile(g_xvc, g_wv, bv, g_vc,
                      (size_t)b * NKM + rt * BM, blockIdx.x * BN, vrows, smh);
    }
}

// Dense GEMM launch (Wo projection).
struct GemmJob { const bf16* A; const bf16* W; const float* bias; bf16* C; };

__global__ __launch_bounds__(256, 2) void gemm_bf16(GemmJob j)
{
    extern __shared__ bf16 smh[];
    gemm_tile(j.A, j.W, j.bias, j.C,
              (size_t)blockIdx.y * BM, blockIdx.x * BN, BM, smh);
}

// ---------------------------------------------------------------------------
// Attention on COMPACTED K/V, 3-stage K/V cp.async ring.
// No masking; pad columns (zero K) contribute exp(0)=1 to the sum,
// corrected exactly by subtracting npad.
// ---------------------------------------------------------------------------
#define LDQ 72
#define LDKV 72
#define KVSTG (64 * LDKV)
#define ATTN_SMEM_BYTES ((128 * LDQ + 6 * KVSTG) * 2)  // 73728

__global__ __launch_bounds__(256, 2) void attn_kernel()
{
    extern __shared__ char smraw[];
    bf16* Qs = (bf16*)smraw;
    bf16* Kb[3]; bf16* Vb[3];
    Kb[0] = Qs + 128 * LDQ;
    Vb[0] = Kb[0] + KVSTG;
    Kb[1] = Vb[0] + KVSTG;
    Vb[1] = Kb[1] + KVSTG;
    Kb[2] = Vb[1] + KVSTG;
    Vb[2] = Kb[2] + KVSTG;

    const int qt = blockIdx.x, h = blockIdx.y, b = blockIdx.z;
    const int tid  = threadIdx.x;
    const int warp = tid >> 5;
    const int lane = tid & 31;
    const int r = lane >> 2;
    const int c = lane & 3;
    const int lr = tid >> 3, lc8 = tid & 7;
    const int lrow8 = lane & 7;
    const int ksel  = (lane >> 3) & 1;
    const int nsel  = (lane >> 4) & 1;
    const int g  = lane >> 3;
    const int rw = lane & 7;

    const int nk = g_nk[b];
    const int KB = (nk + 127) >> 6;
    const float fpad = (float)((KB << 6) - nk - MMEM);

    const bf16* qbase = g_q + ((size_t)(b * NSEQ + qt * 128)) * DMODEL + h * DK;
    const bf16* kroot = g_kc + ((size_t)(b * NKM)) * DMODEL + h * DK;
    const bf16* vroot = g_vc + ((size_t)(b * NKM)) * DMODEL + h * DK;

    // group 0: Q
#pragma unroll
    for (int t = 0; t < 4; t++) {
        int row = lr + t * 32;
        cp16(smem_u32(&Qs[row * LDQ + lc8 * 8]), &qbase[(size_t)row * DMODEL + lc8 * 8]);
    }
    cp_commit();

    // groups 1,2: K/V blocks 0,1 (KB >= 2 always: nk >= 1 -> KB >= 2 when
    // nk > 64; statistically nk ~ 512. Guard anyway.)
    {
#pragma unroll
        for (int t = 0; t < 2; t++) {
            int row = lr + t * 32;
            cp16(smem_u32(&Kb[0][row * LDKV + lc8 * 8]), &kroot[(size_t)row * DMODEL + lc8 * 8]);
            cp16(smem_u32(&Vb[0][row * LDKV + lc8 * 8]), &vroot[(size_t)row * DMODEL + lc8 * 8]);
        }
        cp_commit();
        if (KB > 1) {
            const bf16* kp = kroot + (size_t)64 * DMODEL;
            const bf16* vp = vroot + (size_t)64 * DMODEL;
#pragma unroll
            for (int t = 0; t < 2; t++) {
                int row = lr + t * 32;
                cp16(smem_u32(&Kb[1][row * LDKV + lc8 * 8]), &kp[(size_t)row * DMODEL + lc8 * 8]);
                cp16(smem_u32(&Vb[1][row * LDKV + lc8 * 8]), &vp[(size_t)row * DMODEL + lc8 * 8]);
            }
            cp_commit();
        }
    }

    // Q resident (2 newer K/V groups may be in flight)
    if (KB > 1) cp_wait<2>(); else cp_wait<1>();
    __syncthreads();

    uint32_t qf[4][4];
    {
        uint32_t q0 = smem_u32(&Qs[(warp * 16 + r) * LDQ]) + 4 * c;
        uint32_t q8 = q0 + 8 * LDQ * 2;
#pragma unroll
        for (int kc = 0; kc < 4; kc++) {
            qf[kc][0] = lds_u32(q0 + kc * 32);
            qf[kc][1] = lds_u32(q8 + kc * 32);
            qf[kc][2] = lds_u32(q0 + kc * 32 + 16);
            qf[kc][3] = lds_u32(q8 + kc * 32 + 16);
        }
    }

    float oacc[8][4];
#pragma unroll
    for (int ot = 0; ot < 8; ot++)
#pragma unroll
        for (int i = 0; i < 4; i++) oacc[ot][i] = 0.0f;
    float sum0 = 0.0f, sum1 = 0.0f;

    for (int kb = 0; kb < KB; kb++) {
        const bf16* Kp = Kb[kb % 3];
        const bf16* Vp = Vb[kb % 3];

        // ensure stage kb resident; newest (kb+1) may stay in flight
        if (kb + 1 < KB) cp_wait<1>(); else cp_wait<0>();
        __syncthreads();   // all warps done with the ring slot we prefetch into

        if (kb + 2 < KB) {
            bf16* Kn = Kb[(kb + 2) % 3];
            bf16* Vn = Vb[(kb + 2) % 3];
            const bf16* kp = kroot + (size_t)(kb + 2) * 64 * DMODEL;
            const bf16* vp = vroot + (size_t)(kb + 2) * 64 * DMODEL;
#pragma unroll
            for (int t = 0; t < 2; t++) {
                int row = lr + t * 32;
                cp16(smem_u32(&Kn[row * LDKV + lc8 * 8]), &kp[(size_t)row * DMODEL + lc8 * 8]);
                cp16(smem_u32(&Vn[row * LDKV + lc8 * 8]), &vp[(size_t)row * DMODEL + lc8 * 8]);
            }
            cp_commit();
        }

        float sc[8][4];
#pragma unroll
        for (int nt = 0; nt < 8; nt++)
#pragma unroll
            for (int i = 0; i < 4; i++) sc[nt][i] = 0.0f;

        const uint32_t kfb = smem_u32(Kp) + ((nsel * 8 + lrow8) * LDKV + ksel * 8) * 2;
#pragma unroll
        for (int kc = 0; kc < 4; kc++) {
#pragma unroll
            for (int ng = 0; ng < 4; ng++) {
                uint32_t b0, b1, b2, b3;
                ldsm_x4(b0, b1, b2, b3, kfb + (ng * 16 * LDKV + kc * 16) * 2);
                mma16816(sc[2 * ng][0], sc[2 * ng][1], sc[2 * ng][2], sc[2 * ng][3],
                         qf[kc][0], qf[kc][1], qf[kc][2], qf[kc][3], b0, b1);
                mma16816(sc[2 * ng + 1][0], sc[2 * ng + 1][1], sc[2 * ng + 1][2], sc[2 * ng + 1][3],
                         qf[kc][0], qf[kc][1], qf[kc][2], qf[kc][3], b2, b3);
            }
        }

        uint32_t pf[8][2];
#pragma unroll
        for (int nt = 0; nt < 8; nt++) {
            float p00 = __expf(sc[nt][0] * 0.125f);
            float p01 = __expf(sc[nt][1] * 0.125f);
            float p10 = __expf(sc[nt][2] * 0.125f);
            float p11 = __expf(sc[nt][3] * 0.125f);
            sum0 += p00 + p01;
            sum1 += p10 + p11;
            pf[nt][0] = pack_bf16x2(p00, p01);
            pf[nt][1] = pack_bf16x2(p10, p11);
        }

        const uint32_t vbase = smem_u32(Vp);
#pragma unroll
        for (int kc = 0; kc < 4; kc++) {
            uint32_t a0 = pf[2 * kc][0], a1 = pf[2 * kc][1];
            uint32_t a2 = pf[2 * kc + 1][0], a3 = pf[2 * kc + 1][1];
#pragma unroll
            for (int op = 0; op < 4; op++) {
                uint32_t addr = vbase +
                    ((16 * kc + (g & 1) * 8 + rw) * LDKV + (op * 2 + (g >> 1)) * 8) * 2;
                uint32_t b0, b1, b2, b3;
                ldsm_x4_trans(b0, b1, b2, b3, addr);
                mma16816(oacc[op * 2][0], oacc[op * 2][1], oacc[op * 2][2], oacc[op * 2][3],
                         a0, a1, a2, a3, b0, b1);
                mma16816(oacc[op * 2 + 1][0], oacc[op * 2 + 1][1],
                         oacc[op * 2 + 1][2], oacc[op * 2 + 1][3],
                         a0, a1, a2, a3, b2, b3);
            }
        }
    }

    sum0 += __shfl_xor_sync(0xffffffffu, sum0, 1);
    sum0 += __shfl_xor_sync(0xffffffffu, sum0, 2);
    sum1 += __shfl_xor_sync(0xffffffffu, sum1, 1);
    sum1 += __shfl_xor_sync(0xffffffffu, sum1, 2);
    const float inv0 = 1.0f / (sum0 - fpad);
    const float inv1 = 1.0f / (sum1 - fpad);

    bf16* ob = g_attn + ((size_t)(b * NSEQ + qt * 128 + warp * 16 + r)) * DMODEL + h * DK + 2 * c;
#pragma unroll
    for (int ot = 0; ot < 8; ot++) {
        *(uint32_t*)&ob[ot * 8] =
            pack_bf16x2(oacc[ot][0] * inv0, oacc[ot][1] * inv0);
        *(uint32_t*)&ob[8 * DMODEL + ot * 8] =
            pack_bf16x2(oacc[ot][2] * inv1, oacc[ot][3] * inv1);
    }
}

// ---------------------------------------------------------------------------
// Residual + LayerNorm. One warp per row. proj is bf16.
// ---------------------------------------------------------------------------
__global__ __launch_bounds__(256) void ln_kernel(
    const float* __restrict__ queries, const float* __restrict__ gamma,
    const float* __restrict__ beta, float* __restrict__ out)
{
    const int row  = blockIdx.x * 8 + (threadIdx.x >> 5);
    const int lane = threadIdx.x & 31;
    const float4* xin = (const float4*)(queries + (size_t)row * DMODEL);
    const uint4*  pin = (const uint4*)(g_proj + (size_t)row * DMODEL);

    float x[32];
    float s = 0.0f;
#pragma unroll
    for (int i = 0; i < 4; i++) {
        int ch = lane + i * 32;
        float4 a0 = xin[ch * 2];
        float4 a1 = xin[ch * 2 + 1];
        uint4 p = pin[ch];
        const bf162* ph = (const bf162*)&p;
        float2 p0 = __bfloat1622float2(ph[0]);
        float2 p1 = __bfloat1622float2(ph[1]);
        float2 p2 = __bfloat1622float2(ph[2]);
        float2 p3 = __bfloat1622float2(ph[3]);
        x[i * 8 + 0] = a0.x + p0.x; x[i * 8 + 1] = a0.y + p0.y;
        x[i * 8 + 2] = a0.z + p1.x; x[i * 8 + 3] = a0.w + p1.y;
        x[i * 8 + 4] = a1.x + p2.x; x[i * 8 + 5] = a1.y + p2.y;
        x[i * 8 + 6] = a1.z + p3.x; x[i * 8 + 7] = a1.w + p3.y;
#pragma unroll
        for (int k = 0; k < 8; k++) s += x[i * 8 + k];
    }
#pragma unroll
    for (int o = 16; o; o >>= 1) s += __shfl_xor_sync(0xffffffffu, s, o);
    const float mu = s * (1.0f / DMODEL);

    float v = 0.0f;
#pragma unroll
    for (int i = 0; i < 32; i++) { float d = x[i] - mu; v += d * d; }
#pragma unroll
    for (int o = 16; o; o >>= 1) v += __shfl_xor_sync(0xffffffffu, v, o);
    const float rs = rsqrtf(v * (1.0f / DMODEL) + EPS);

    float4* op = (float4*)(out + (size_t)row * DMODEL);
    const float4* gp = (const float4*)gamma;
    const float4* bp = (const float4*)beta;
#pragma unroll
    for (int i = 0; i < 4; i++) {
        int ch = lane + i * 32;
#pragma unroll
        for (int half = 0; half < 2; half++) {
            float4 g  = gp[ch * 2 + half];
            float4 be = bp[ch * 2 + half];
            float4 o4;
            o4.x = (x[i * 8 + half * 4 + 0] - mu) * rs * g.x + be.x;
            o4.y = (x[i * 8 + half * 4 + 1] - mu) * rs * g.y + be.y;
            o4.z = (x[i * 8 + half * 4 + 2] - mu) * rs * g.z + be.z;
            o4.w = (x[i * 8 + half * 4 + 3] - mu) * rs * g.w + be.w;
            op[ch * 2 + half] = o4;
        }
    }
}

// ---------------------------------------------------------------------------
// Launch
// ---------------------------------------------------------------------------
extern "C" void kernel_launch(void* const* d_in, const int* in_sizes, int n_in,
                              void* d_out, int out_size)
{
    const float* queries = (const float*)d_in[0];
    const float* keys    = (const float*)d_in[1];
    const float* values  = (const float*)d_in[2];
    const int*   amask   = (const int*)  d_in[3];
    const float* Wq = (const float*)d_in[4],  *bq = (const float*)d_in[5];
    const float* Wk = (const float*)d_in[6],  *bk = (const float*)d_in[7];
    const float* Wv = (const float*)d_in[8],  *bv = (const float*)d_in[9];
    const float* Wo = (const float*)d_in[10], *bo = (const float*)d_in[11];
    const float* m_k = (const float*)d_in[12], *m_v = (const float*)d_in[13];
    const float* gamma = (const float*)d_in[14], *beta = (const float*)d_in[15];
    float* out = (float*)d_out;

    bf16 *xq, *wq, *wk, *wv, *wo, *pa, *pp;
    cudaGetSymbolAddress((void**)&xq, g_xq);
    cudaGetSymbolAddress((void**)&wq, g_wq);
    cudaGetSymbolAddress((void**)&wk, g_wk);
    cudaGetSymbolAddress((void**)&wv, g_wv);
    cudaGetSymbolAddress((void**)&wo, g_wo);
    cudaGetSymbolAddress((void**)&pa, g_attn);
    cudaGetSymbolAddress((void**)&pp, g_proj);

    cudaFuncSetAttribute(proj_gemm,
                         cudaFuncAttributeMaxDynamicSharedMemorySize, GEMM_SMEM_BYTES);
    cudaFuncSetAttribute(gemm_bf16,
                         cudaFuncAttributeMaxDynamicSharedMemorySize, GEMM_SMEM_BYTES);
    cudaFuncSetAttribute(attn_kernel,
                         cudaFuncAttributeMaxDynamicSharedMemorySize, ATTN_SMEM_BYTES);

    const int Mrows = BATCH * NSEQ;        // 4096
    const int NACT  = Mrows * DMODEL;      // 4M
    const int NWEI  = DMODEL * DMODEL;     // 1M

    CvtJob cj0 = { queries, xq, NACT };
    CvtJob cj1 = { Wq, wq, NWEI };
    CvtJob cj2 = { Wk, wk, NWEI };
    CvtJob cj3 = { Wv, wv, NWEI };
    CvtJob cj4 = { Wo, wo, NWEI };
    // grid.y: 0..4 = conversions, 5 = mask scan
    cvt_all<<<dim3(NACT / 2048, 6), 256>>>(cj0, cj1, cj2, cj3, cj4, amask);

    // compact inputs + memory rows + zero pad (one launch)
    compact_in<<<dim3(NSEQ + MMEM + 64, BATCH), 128>>>(keys, values, m_k, m_v);

    // merged Q/K/V projections (Q dense; K/V compacted, predicated stores)
    proj_gemm<<<dim3(DMODEL / BN, Mrows / BM, 3), 256, GEMM_SMEM_BYTES>>>(bq, bk, bv);

    // attention over compacted keys (3-stage K/V pipeline)
    attn_kernel<<<dim3(NSEQ / 128, NHEAD, BATCH), 256, ATTN_SMEM_BYTES>>>();

    // output projection
    GemmJob jo = { pa, wo, bo, pp };
    gemm_bf16<<<dim3(DMODEL / BN, Mrows / BM, 1), 256, GEMM_SMEM_BYTES>>>(jo);

    ln_kernel<<<Mrows / 8, 256>>>(queries, gamma, beta, out);
}